// round 1
// baseline (speedup 1.0000x reference)
#include <cuda_runtime.h>
#include <math.h>

#define TOK 32768
#define CDIM 256
#define MLPD 1024

// ---------------- device scratch (no allocations allowed) ----------------
__device__ float g_xw[TOK * CDIM];      // LN1 output, window-gathered order
__device__ float g_q[TOK * CDIM];       // [512][8][64][32]
__device__ float g_k[TOK * CDIM];
__device__ float g_v[TOK * CDIM];
__device__ float g_ctx[TOK * CDIM];     // [win*64+n][256] windowed order
__device__ float g_hidden[TOK * CDIM];  // residual after attention (orig order)
__device__ float g_y[TOK * CDIM];       // LN2 output
__device__ float g_inter[TOK * MLPD];   // MLP hidden

// windowed token index -> original token index (+4 cyclic shift both ways)
__device__ __forceinline__ int map_shift(int t) {
  int b = t >> 12, rr = t & 4095;
  int win = rr >> 6, n = rr & 63;
  int wh = win >> 3, ww = win & 7, i = n >> 3, j = n & 7;
  int h = (wh * 8 + i + 4) & 63;
  int w = (ww * 8 + j + 4) & 63;
  return (b << 12) + (h << 6) + w;
}

// ---------------- LayerNorm (one warp per token) ----------------
template <bool GATHER>
__global__ void __launch_bounds__(256) ln_kernel(
    const float* __restrict__ x, const float* __restrict__ gam,
    const float* __restrict__ bet, float* __restrict__ out) {
  int warp = threadIdx.x >> 5, lane = threadIdx.x & 31;
  int t = blockIdx.x * 8 + warp;
  int src = GATHER ? map_shift(t) : t;
  const float4* xr = (const float4*)(x + (size_t)src * CDIM);
  float4 v0 = xr[lane], v1 = xr[lane + 32];
  float s = v0.x + v0.y + v0.z + v0.w + v1.x + v1.y + v1.z + v1.w;
  float q = v0.x * v0.x + v0.y * v0.y + v0.z * v0.z + v0.w * v0.w +
            v1.x * v1.x + v1.y * v1.y + v1.z * v1.z + v1.w * v1.w;
#pragma unroll
  for (int o = 16; o; o >>= 1) {
    s += __shfl_xor_sync(0xffffffffu, s, o);
    q += __shfl_xor_sync(0xffffffffu, q, o);
  }
  float mean = s * (1.0f / 256.0f);
  float var = q * (1.0f / 256.0f) - mean * mean;
  float rs = rsqrtf(var + 1e-5f);
  const float4* g4 = (const float4*)gam;
  const float4* b4 = (const float4*)bet;
  float4* ow = (float4*)(out + (size_t)t * CDIM);
  {
    float4 ga = g4[lane], be = b4[lane], o0;
    o0.x = (v0.x - mean) * rs * ga.x + be.x;
    o0.y = (v0.y - mean) * rs * ga.y + be.y;
    o0.z = (v0.z - mean) * rs * ga.z + be.z;
    o0.w = (v0.w - mean) * rs * ga.w + be.w;
    ow[lane] = o0;
  }
  {
    float4 ga = g4[lane + 32], be = b4[lane + 32], o1;
    o1.x = (v1.x - mean) * rs * ga.x + be.x;
    o1.y = (v1.y - mean) * rs * ga.y + be.y;
    o1.z = (v1.z - mean) * rs * ga.z + be.z;
    o1.w = (v1.w - mean) * rs * ga.w + be.w;
    ow[lane + 32] = o1;
  }
}

// ---------------- 128x128x8 SGEMM, out = A @ W^T + bias, epilogue variants --
// EPI 0: QKV store permuted to [win][head][n][d]
// EPI 1: WO: scatter to original token + residual (extra = shortcut)
// EPI 2: MLP1: exact GELU
// EPI 3: MLP2: + extra (residual), row-major store
template <int EPI>
__global__ void __launch_bounds__(256, 2) gemm_k(
    const float* __restrict__ A, const float* __restrict__ W,
    const float* __restrict__ bias, float* __restrict__ out,
    int M, int Nn, int K, const float* __restrict__ extra) {
  __shared__ float As[8][128];
  __shared__ float Bs[8][128];
  int tid = threadIdx.x;
  int row0 = blockIdx.y * 128;
  int col0 = blockIdx.x * 128;
  int ty = tid >> 4, tx = tid & 15;
  float acc[8][8];
#pragma unroll
  for (int i = 0; i < 8; i++)
#pragma unroll
    for (int j = 0; j < 8; j++) acc[i][j] = 0.0f;

  int lrow = tid >> 1;
  int lk = (tid & 1) * 4;
  const float* Ap = A + (size_t)(row0 + lrow) * K + lk;
  const float* Wp = W + (size_t)(col0 + lrow) * K + lk;

  for (int k0 = 0; k0 < K; k0 += 8) {
    float4 av = *(const float4*)(Ap + k0);
    float4 wv = *(const float4*)(Wp + k0);
    __syncthreads();
    As[lk + 0][lrow] = av.x;
    As[lk + 1][lrow] = av.y;
    As[lk + 2][lrow] = av.z;
    As[lk + 3][lrow] = av.w;
    Bs[lk + 0][lrow] = wv.x;
    Bs[lk + 1][lrow] = wv.y;
    Bs[lk + 2][lrow] = wv.z;
    Bs[lk + 3][lrow] = wv.w;
    __syncthreads();
#pragma unroll
    for (int kk = 0; kk < 8; kk++) {
      float4 a0 = *(const float4*)&As[kk][ty * 8];
      float4 a1 = *(const float4*)&As[kk][ty * 8 + 4];
      float4 b0 = *(const float4*)&Bs[kk][tx * 8];
      float4 b1 = *(const float4*)&Bs[kk][tx * 8 + 4];
      float ar[8] = {a0.x, a0.y, a0.z, a0.w, a1.x, a1.y, a1.z, a1.w};
      float br[8] = {b0.x, b0.y, b0.z, b0.w, b1.x, b1.y, b1.z, b1.w};
#pragma unroll
      for (int i = 0; i < 8; i++)
#pragma unroll
        for (int j = 0; j < 8; j++) acc[i][j] = fmaf(ar[i], br[j], acc[i][j]);
    }
  }

#pragma unroll
  for (int i = 0; i < 8; i++) {
    int r = row0 + ty * 8 + i;
    if (EPI == 0) {
      int win = r >> 6, n = r & 63;
      size_t rbase = (size_t)win * 16384 + (size_t)n * 32;
#pragma unroll
      for (int j = 0; j < 8; j++) {
        int c = col0 + tx * 8 + j;
        int head = c >> 5, d = c & 31;
        out[rbase + head * 2048 + d] = acc[i][j] + bias[c];
      }
    } else if (EPI == 1) {
      int dst = map_shift(r);
      size_t off = (size_t)dst * 256 + col0 + tx * 8;
#pragma unroll
      for (int j = 0; j < 8; j++) {
        int c = col0 + tx * 8 + j;
        out[off + j] = acc[i][j] + bias[c] + extra[off + j];
      }
    } else if (EPI == 2) {
      float tmp[8];
#pragma unroll
      for (int j = 0; j < 8; j++) {
        int c = col0 + tx * 8 + j;
        float v = acc[i][j] + bias[c];
        tmp[j] = 0.5f * v * (1.0f + erff(v * 0.7071067811865476f));
      }
      float4* op = (float4*)(out + (size_t)r * Nn + col0 + tx * 8);
      op[0] = make_float4(tmp[0], tmp[1], tmp[2], tmp[3]);
      op[1] = make_float4(tmp[4], tmp[5], tmp[6], tmp[7]);
    } else {
      size_t off = (size_t)r * 256 + col0 + tx * 8;
      float tmp[8];
#pragma unroll
      for (int j = 0; j < 8; j++) {
        int c = col0 + tx * 8 + j;
        tmp[j] = acc[i][j] + bias[c] + extra[off + j];
      }
      float4* op = (float4*)(out + off);
      op[0] = make_float4(tmp[0], tmp[1], tmp[2], tmp[3]);
      op[1] = make_float4(tmp[4], tmp[5], tmp[6], tmp[7]);
    }
  }
}

// ---------------- windowed attention: one block per (window, head) ---------
__global__ void __launch_bounds__(256) attn_kernel(
    const float* __restrict__ rel_table) {
  __shared__ float qs[64 * 32];
  __shared__ float kT[32 * 64];   // k-major transposed K
  __shared__ float vs[64 * 32];
  __shared__ float Ps[64 * 64];
  __shared__ float rel_s[225];
  __shared__ int rid_s[64];

  int tid = threadIdx.x;
  int gw = blockIdx.x;          // 0..511  (b*64 + window)
  int head = blockIdx.y;        // 0..7
  size_t base = ((size_t)gw * 8 + head) * 2048;
  const float4* qg = (const float4*)(g_q + base);
  const float4* kg = (const float4*)(g_k + base);
  const float4* vg = (const float4*)(g_v + base);
  ((float4*)qs)[tid] = qg[tid];
  ((float4*)qs)[tid + 256] = qg[tid + 256];
  ((float4*)vs)[tid] = vg[tid];
  ((float4*)vs)[tid + 256] = vg[tid + 256];
#pragma unroll
  for (int it = tid; it < 512; it += 256) {
    float4 kv4 = kg[it];
    int row = it >> 3;
    int c = (it & 7) * 4;
    kT[(c + 0) * 64 + row] = kv4.x;
    kT[(c + 1) * 64 + row] = kv4.y;
    kT[(c + 2) * 64 + row] = kv4.z;
    kT[(c + 3) * 64 + row] = kv4.w;
  }
  if (tid < 225) rel_s[tid] = rel_table[tid * 8 + head];
  if (tid < 64) {
    int nw = gw & 63;
    int h = (nw >> 3) * 8 + (tid >> 3);
    int w = (nw & 7) * 8 + (tid & 7);
    int rh = h < 56 ? 0 : (h < 60 ? 1 : 2);
    int rw = w < 56 ? 0 : (w < 60 ? 1 : 2);
    rid_s[tid] = rh * 3 + rw;
  }
  __syncthreads();

  // S = Q @ K^T : each thread 4 rows x 4 cols
  int r0 = (tid >> 4) * 4;
  int c0 = (tid & 15) * 4;
  float acc[4][4];
#pragma unroll
  for (int u = 0; u < 4; u++)
#pragma unroll
    for (int v = 0; v < 4; v++) acc[u][v] = 0.0f;
#pragma unroll
  for (int kk = 0; kk < 32; kk++) {
    float qr[4];
#pragma unroll
    for (int u = 0; u < 4; u++) qr[u] = qs[(r0 + u) * 32 + kk];
    float4 kv = *(const float4*)&kT[kk * 64 + c0];
    float kr[4] = {kv.x, kv.y, kv.z, kv.w};
#pragma unroll
    for (int u = 0; u < 4; u++)
#pragma unroll
      for (int v = 0; v < 4; v++) acc[u][v] = fmaf(qr[u], kr[v], acc[u][v]);
  }
  const float scale = 0.17677669529663687f;  // 1/sqrt(32)
#pragma unroll
  for (int u = 0; u < 4; u++) {
    int n = r0 + u;
    int in_ = n >> 3, jn = n & 7;
    int ridn = rid_s[n];
    float tmp[4];
#pragma unroll
    for (int v = 0; v < 4; v++) {
      int m = c0 + v;
      int di = in_ - (m >> 3) + 7;
      int dj = jn - (m & 7) + 7;
      float sv = acc[u][v] * scale + rel_s[di * 15 + dj];
      if (ridn != rid_s[m]) sv -= 100.0f;
      tmp[v] = sv;
    }
    *(float4*)&Ps[n * 64 + c0] = make_float4(tmp[0], tmp[1], tmp[2], tmp[3]);
  }
  __syncthreads();

  // softmax over rows (8 rows per warp)
  int warp = tid >> 5, lane = tid & 31;
#pragma unroll
  for (int rr = 0; rr < 8; rr++) {
    int row = warp * 8 + rr;
    float a = Ps[row * 64 + lane];
    float b = Ps[row * 64 + lane + 32];
    float mx = fmaxf(a, b);
#pragma unroll
    for (int o = 16; o; o >>= 1) mx = fmaxf(mx, __shfl_xor_sync(0xffffffffu, mx, o));
    float e1 = __expf(a - mx), e2 = __expf(b - mx);
    float sm = e1 + e2;
#pragma unroll
    for (int o = 16; o; o >>= 1) sm += __shfl_xor_sync(0xffffffffu, sm, o);
    float inv = 1.0f / sm;
    Ps[row * 64 + lane] = e1 * inv;
    Ps[row * 64 + lane + 32] = e2 * inv;
  }
  __syncthreads();

  // ctx = P @ V : each thread one row, 8 d-values
  int row = tid >> 2;
  int db = (tid & 3) * 8;
  float o[8];
#pragma unroll
  for (int u = 0; u < 8; u++) o[u] = 0.0f;
#pragma unroll
  for (int m = 0; m < 64; m++) {
    float p = Ps[row * 64 + m];
    float4 va = *(const float4*)&vs[m * 32 + db];
    float4 vb = *(const float4*)&vs[m * 32 + db + 4];
    o[0] = fmaf(p, va.x, o[0]);
    o[1] = fmaf(p, va.y, o[1]);
    o[2] = fmaf(p, va.z, o[2]);
    o[3] = fmaf(p, va.w, o[3]);
    o[4] = fmaf(p, vb.x, o[4]);
    o[5] = fmaf(p, vb.y, o[5]);
    o[6] = fmaf(p, vb.z, o[6]);
    o[7] = fmaf(p, vb.w, o[7]);
  }
  float* cp = g_ctx + ((size_t)gw * 64 + row) * 256 + head * 32 + db;
  *(float4*)cp = make_float4(o[0], o[1], o[2], o[3]);
  *(float4*)(cp + 4) = make_float4(o[4], o[5], o[6], o[7]);
}

// ---------------- host ----------------
extern "C" void kernel_launch(void* const* d_in, const int* in_sizes, int n_in,
                              void* d_out, int out_size) {
  (void)in_sizes; (void)n_in; (void)out_size;
  const float* hs   = (const float*)d_in[0];
  const float* ln1g = (const float*)d_in[1];
  const float* ln1b = (const float*)d_in[2];
  const float* wq   = (const float*)d_in[3];
  const float* bq   = (const float*)d_in[4];
  const float* wk   = (const float*)d_in[5];
  const float* bk   = (const float*)d_in[6];
  const float* wv   = (const float*)d_in[7];
  const float* bv   = (const float*)d_in[8];
  const float* rel  = (const float*)d_in[9];
  const float* wo   = (const float*)d_in[10];
  const float* bo   = (const float*)d_in[11];
  const float* ln2g = (const float*)d_in[12];
  const float* ln2b = (const float*)d_in[13];
  const float* w1   = (const float*)d_in[14];
  const float* b1   = (const float*)d_in[15];
  const float* w2   = (const float*)d_in[16];
  const float* b2   = (const float*)d_in[17];
  float* out = (float*)d_out;

  float *xw, *q, *k, *v, *ctx, *hid, *y, *inter;
  cudaGetSymbolAddress((void**)&xw, g_xw);
  cudaGetSymbolAddress((void**)&q, g_q);
  cudaGetSymbolAddress((void**)&k, g_k);
  cudaGetSymbolAddress((void**)&v, g_v);
  cudaGetSymbolAddress((void**)&ctx, g_ctx);
  cudaGetSymbolAddress((void**)&hid, g_hidden);
  cudaGetSymbolAddress((void**)&y, g_y);
  cudaGetSymbolAddress((void**)&inter, g_inter);

  ln_kernel<true><<<4096, 256>>>(hs, ln1g, ln1b, xw);

  dim3 g2(2, 256);
  gemm_k<0><<<g2, 256>>>(xw, wq, bq, q, TOK, 256, 256, nullptr);
  gemm_k<0><<<g2, 256>>>(xw, wk, bk, k, TOK, 256, 256, nullptr);
  gemm_k<0><<<g2, 256>>>(xw, wv, bv, v, TOK, 256, 256, nullptr);

  attn_kernel<<<dim3(512, 8), 256>>>(rel);

  gemm_k<1><<<g2, 256>>>(ctx, wo, bo, hid, TOK, 256, 256, hs);

  ln_kernel<false><<<4096, 256>>>(hid, ln2g, ln2b, y);

  gemm_k<2><<<dim3(8, 256), 256>>>(y, w1, b1, inter, TOK, 1024, 256, nullptr);
  gemm_k<3><<<g2, 256>>>(inter, w2, b2, out, TOK, 256, 1024, hid);
}

// round 3
// speedup vs baseline: 1.8276x; 1.8276x over previous
#include <cuda_runtime.h>
#include <cuda_bf16.h>
#include <math.h>
#include <stdint.h>

#define TOK 32768
#define CDIM 256
#define MLPD 1024

// ---------------- device scratch ----------------
__device__ __nv_bfloat16 g_xw_hi[TOK * CDIM], g_xw_lo[TOK * CDIM];
__device__ __nv_bfloat16 g_y_hi[TOK * CDIM], g_y_lo[TOK * CDIM];
__device__ __nv_bfloat16 g_ctx_hi[TOK * CDIM], g_ctx_lo[TOK * CDIM];
__device__ __nv_bfloat16 g_int_hi[TOK * MLPD], g_int_lo[TOK * MLPD];
__device__ __nv_bfloat16 g_wqkv_hi[3 * CDIM * CDIM], g_wqkv_lo[3 * CDIM * CDIM];
__device__ __nv_bfloat16 g_wo_hi[CDIM * CDIM], g_wo_lo[CDIM * CDIM];
__device__ __nv_bfloat16 g_w1_hi[MLPD * CDIM], g_w1_lo[MLPD * CDIM];
__device__ __nv_bfloat16 g_w2_hi[CDIM * MLPD], g_w2_lo[CDIM * MLPD];
__device__ float g_bqkv[3 * CDIM];
__device__ float g_qkv[3 * TOK * CDIM];   // [sel][win][head][n][d]
__device__ float g_hidden[TOK * CDIM];

// ---------------- helpers ----------------
__device__ __forceinline__ uint32_t smem_u32(const void* p) {
  uint32_t a;
  asm("{ .reg .u64 t; cvta.to.shared.u64 t, %1; cvt.u32.u64 %0, t; }"
      : "=r"(a) : "l"(p));
  return a;
}

#define LDSM4(r, addr) \
  asm volatile("ldmatrix.sync.aligned.m8n8.x4.shared.b16 {%0,%1,%2,%3}, [%4];" \
               : "=r"((r)[0]), "=r"((r)[1]), "=r"((r)[2]), "=r"((r)[3]) \
               : "r"(addr))

#define MMA16816(d, a, b0, b1) \
  asm volatile( \
      "mma.sync.aligned.m16n8k16.row.col.f32.bf16.bf16.f32 " \
      "{%0,%1,%2,%3}, {%4,%5,%6,%7}, {%8,%9}, {%0,%1,%2,%3};" \
      : "+f"((d)[0]), "+f"((d)[1]), "+f"((d)[2]), "+f"((d)[3]) \
      : "r"((a)[0]), "r"((a)[1]), "r"((a)[2]), "r"((a)[3]), \
        "r"(b0), "r"(b1))

__device__ __forceinline__ void split2(float x, __nv_bfloat16& h, __nv_bfloat16& l) {
  h = __float2bfloat16(x);
  l = __float2bfloat16(x - __bfloat162float(h));
}

// windowed token index -> original token index (+4 cyclic shift)
__device__ __forceinline__ int map_shift(int t) {
  int b = t >> 12, rr = t & 4095;
  int win = rr >> 6, n = rr & 63;
  int wh = win >> 3, ww = win & 7, i = n >> 3, j = n & 7;
  int h = (wh * 8 + i + 4) & 63;
  int w = (ww * 8 + j + 4) & 63;
  return (b << 12) + (h << 6) + w;
}

// ---------------- LayerNorm -> bf16 split (one warp per token) -------------
template <bool GATHER>
__global__ void __launch_bounds__(256) ln_split(
    const float* __restrict__ x, const float* __restrict__ gam,
    const float* __restrict__ bet, __nv_bfloat16* __restrict__ ohi,
    __nv_bfloat16* __restrict__ olo) {
  int warp = threadIdx.x >> 5, lane = threadIdx.x & 31;
  int t = blockIdx.x * 8 + warp;
  int src = GATHER ? map_shift(t) : t;
  const float4* xr = (const float4*)(x + (size_t)src * CDIM);
  float4 v0 = xr[lane], v1 = xr[lane + 32];
  float s = v0.x + v0.y + v0.z + v0.w + v1.x + v1.y + v1.z + v1.w;
  float q = v0.x * v0.x + v0.y * v0.y + v0.z * v0.z + v0.w * v0.w +
            v1.x * v1.x + v1.y * v1.y + v1.z * v1.z + v1.w * v1.w;
#pragma unroll
  for (int o = 16; o; o >>= 1) {
    s += __shfl_xor_sync(0xffffffffu, s, o);
    q += __shfl_xor_sync(0xffffffffu, q, o);
  }
  float mean = s * (1.0f / 256.0f);
  float var = q * (1.0f / 256.0f) - mean * mean;
  float rs = rsqrtf(var + 1e-5f);
  const float4* g4 = (const float4*)gam;
  const float4* b4 = (const float4*)bet;
  __nv_bfloat16 h[4], l[4];
  {
    float4 ga = g4[lane], be = b4[lane];
    split2((v0.x - mean) * rs * ga.x + be.x, h[0], l[0]);
    split2((v0.y - mean) * rs * ga.y + be.y, h[1], l[1]);
    split2((v0.z - mean) * rs * ga.z + be.z, h[2], l[2]);
    split2((v0.w - mean) * rs * ga.w + be.w, h[3], l[3]);
    *(uint2*)(ohi + (size_t)t * CDIM + lane * 4) = *(uint2*)h;
    *(uint2*)(olo + (size_t)t * CDIM + lane * 4) = *(uint2*)l;
  }
  {
    float4 ga = g4[lane + 32], be = b4[lane + 32];
    split2((v1.x - mean) * rs * ga.x + be.x, h[0], l[0]);
    split2((v1.y - mean) * rs * ga.y + be.y, h[1], l[1]);
    split2((v1.z - mean) * rs * ga.z + be.z, h[2], l[2]);
    split2((v1.w - mean) * rs * ga.w + be.w, h[3], l[3]);
    *(uint2*)(ohi + (size_t)t * CDIM + 128 + lane * 4) = *(uint2*)h;
    *(uint2*)(olo + (size_t)t * CDIM + 128 + lane * 4) = *(uint2*)l;
  }
}

// ---------------- weight split / bias concat ----------------
__global__ void split_w(const float* __restrict__ src, __nv_bfloat16* __restrict__ hi,
                        __nv_bfloat16* __restrict__ lo, int n) {
  int i = blockIdx.x * 256 + threadIdx.x;
  if (i < n) {
    float x = src[i];
    __nv_bfloat16 h = __float2bfloat16(x);
    hi[i] = h;
    lo[i] = __float2bfloat16(x - __bfloat162float(h));
  }
}

__global__ void concat_bias(const float* __restrict__ a, const float* __restrict__ b,
                            const float* __restrict__ c) {
  int i = blockIdx.x * 256 + threadIdx.x;
  if (i < 256) g_bqkv[i] = a[i];
  else if (i < 512) g_bqkv[i] = b[i - 256];
  else if (i < 768) g_bqkv[i] = c[i - 512];
}

// ---------------- HMMA bf16-split GEMM: out = A @ W^T (+bias, epilogue) ----
// A: [M][K] hi/lo bf16 row-major, B(W): [Ntot][K] hi/lo bf16 row-major.
// CTA tile 128x128, K-slab 32, double-buffered SMEM (80B row stride),
// warp tile 64x32, mma.sync m16n8k16, 3 split passes (hh, hl, lh).
// EPI 0: QKV permute  1: WO scatter+residual  2: GELU->bf16 split  3: +residual
template <int EPI>
__global__ void __launch_bounds__(256, 1) gemm_mma(
    const __nv_bfloat16* __restrict__ Ahi, const __nv_bfloat16* __restrict__ Alo,
    const __nv_bfloat16* __restrict__ Bhi, const __nv_bfloat16* __restrict__ Blo,
    const float* __restrict__ bias, float* __restrict__ out,
    __nv_bfloat16* __restrict__ out_hi, __nv_bfloat16* __restrict__ out_lo,
    const float* __restrict__ extra, int K) {
  extern __shared__ char smraw[];
  const int STG = 40960;  // 4 arrays * 128 rows * 80 B
  int tid = threadIdx.x, wid = tid >> 5, lane = tid & 31;
  int warp_row = wid >> 2, warp_col = wid & 3;
  int row0 = blockIdx.y * 128, col0 = blockIdx.x * 128;
  uint32_t smem_base = smem_u32(smraw);

  float acc[4][4][4];
#pragma unroll
  for (int mi = 0; mi < 4; mi++)
#pragma unroll
    for (int ni = 0; ni < 4; ni++)
#pragma unroll
      for (int u = 0; u < 4; u++) acc[mi][ni][u] = 0.0f;

  int lrow = tid >> 2;   // 0..63
  int lchunk = tid & 3;  // 16B chunk within 64B k-slab row

  int nslabs = K >> 5;
  uint4 ra[2], rb[2], rc[2], rd[2];

  // ldmatrix lane addressing
  int a_r = warp_row * 64 + (lane & 15);
  int b_r = warp_col * 32 + (lane & 15);
  int oct = lane >> 4;  // 0/1

  // prefetch slab 0
  {
    int k0 = 0;
#pragma unroll
    for (int r = 0; r < 2; r++) {
      int row = lrow + r * 64;
      size_t aoff = (size_t)(row0 + row) * K + k0 + lchunk * 8;
      size_t boff = (size_t)(col0 + row) * K + k0 + lchunk * 8;
      ra[r] = *(const uint4*)(Ahi + aoff);
      rb[r] = *(const uint4*)(Alo + aoff);
      rc[r] = *(const uint4*)(Bhi + boff);
      rd[r] = *(const uint4*)(Blo + boff);
    }
  }

  for (int s = 0; s < nslabs; s++) {
    int buf = s & 1;
    // store current slab
    {
      char* base = smraw + buf * STG;
#pragma unroll
      for (int r = 0; r < 2; r++) {
        int row = lrow + r * 64;
        uint32_t off = row * 80 + lchunk * 16;
        *(uint4*)(base + off) = ra[r];
        *(uint4*)(base + 10240 + off) = rb[r];
        *(uint4*)(base + 20480 + off) = rc[r];
        *(uint4*)(base + 30720 + off) = rd[r];
      }
    }
    // prefetch next slab
    if (s + 1 < nslabs) {
      int k0 = (s + 1) * 32;
#pragma unroll
      for (int r = 0; r < 2; r++) {
        int row = lrow + r * 64;
        size_t aoff = (size_t)(row0 + row) * K + k0 + lchunk * 8;
        size_t boff = (size_t)(col0 + row) * K + k0 + lchunk * 8;
        ra[r] = *(const uint4*)(Ahi + aoff);
        rb[r] = *(const uint4*)(Alo + aoff);
        rc[r] = *(const uint4*)(Bhi + boff);
        rd[r] = *(const uint4*)(Blo + boff);
      }
    }
    __syncthreads();
    // compute from buf
    uint32_t st = smem_base + buf * STG;
#pragma unroll
    for (int kk = 0; kk < 2; kk++) {
      uint32_t ah[4][4], al[4][4];
#pragma unroll
      for (int mi = 0; mi < 4; mi++) {
        uint32_t addr = st + (a_r + mi * 16) * 80 + (2 * kk + oct) * 16;
        LDSM4(ah[mi], addr);
        LDSM4(al[mi], addr + 10240);
      }
      uint32_t bh[2][4], bl[2][4];
#pragma unroll
      for (int nb = 0; nb < 2; nb++) {
        uint32_t addr = st + 20480 + (b_r + nb * 16) * 80 + (2 * kk + oct) * 16;
        LDSM4(bh[nb], addr);
        LDSM4(bl[nb], addr + 10240);
      }
#pragma unroll
      for (int mi = 0; mi < 4; mi++)
#pragma unroll
        for (int ni = 0; ni < 4; ni++) {
          int nb = ni >> 1, up = ni & 1;
          MMA16816(acc[mi][ni], ah[mi], bh[nb][up], bh[nb][up + 2]);
          MMA16816(acc[mi][ni], ah[mi], bl[nb][up], bl[nb][up + 2]);
          MMA16816(acc[mi][ni], al[mi], bh[nb][up], bh[nb][up + 2]);
        }
    }
    __syncthreads();
  }

  // ---------------- epilogue ----------------
  int group = lane >> 2, tig = lane & 3;
#pragma unroll
  for (int mi = 0; mi < 4; mi++) {
#pragma unroll
    for (int half = 0; half < 2; half++) {
      int r = row0 + warp_row * 64 + mi * 16 + group + 8 * half;
      if (EPI == 0) {
        int win = r >> 6, n = r & 63;
#pragma unroll
        for (int ni = 0; ni < 4; ni++) {
          int c = col0 + warp_col * 32 + ni * 8 + tig * 2;
          int sel = c >> 8, cw = c & 255;
          int head = cw >> 5, d = cw & 31;
          float2 bb = *(const float2*)(bias + c);
          float2 v;
          v.x = acc[mi][ni][2 * half + 0] + bb.x;
          v.y = acc[mi][ni][2 * half + 1] + bb.y;
          *(float2*)(out + (size_t)sel * (TOK * CDIM) + (size_t)win * 16384 +
                     head * 2048 + n * 32 + d) = v;
        }
      } else if (EPI == 1) {
        int dst = map_shift(r);
#pragma unroll
        for (int ni = 0; ni < 4; ni++) {
          int c = col0 + warp_col * 32 + ni * 8 + tig * 2;
          size_t off = (size_t)dst * 256 + c;
          float2 bb = *(const float2*)(bias + c);
          float2 ex = *(const float2*)(extra + off);
          float2 v;
          v.x = acc[mi][ni][2 * half + 0] + bb.x + ex.x;
          v.y = acc[mi][ni][2 * half + 1] + bb.y + ex.y;
          *(float2*)(out + off) = v;
        }
      } else if (EPI == 2) {
#pragma unroll
        for (int ni = 0; ni < 4; ni++) {
          int c = col0 + warp_col * 32 + ni * 8 + tig * 2;
          size_t off = (size_t)r * MLPD + c;
          float2 bb = *(const float2*)(bias + c);
          float v0 = acc[mi][ni][2 * half + 0] + bb.x;
          float v1 = acc[mi][ni][2 * half + 1] + bb.y;
          v0 = 0.5f * v0 * (1.0f + erff(v0 * 0.7071067811865476f));
          v1 = 0.5f * v1 * (1.0f + erff(v1 * 0.7071067811865476f));
          __nv_bfloat16 h0, l0, h1, l1;
          split2(v0, h0, l0);
          split2(v1, h1, l1);
          __nv_bfloat162 hh, ll;
          hh.x = h0; hh.y = h1;
          ll.x = l0; ll.y = l1;
          *(__nv_bfloat162*)(out_hi + off) = hh;
          *(__nv_bfloat162*)(out_lo + off) = ll;
        }
      } else {
#pragma unroll
        for (int ni = 0; ni < 4; ni++) {
          int c = col0 + warp_col * 32 + ni * 8 + tig * 2;
          size_t off = (size_t)r * 256 + c;
          float2 bb = *(const float2*)(bias + c);
          float2 ex = *(const float2*)(extra + off);
          float2 v;
          v.x = acc[mi][ni][2 * half + 0] + bb.x + ex.x;
          v.y = acc[mi][ni][2 * half + 1] + bb.y + ex.y;
          *(float2*)(out + off) = v;
        }
      }
    }
  }
}

// ---------------- windowed attention: one block per (window, head) ---------
__global__ void __launch_bounds__(256) attn_kernel(
    const float* __restrict__ rel_table) {
  __shared__ float qs[64 * 32];
  __shared__ float kT[32 * 64];
  __shared__ float vs[64 * 32];
  __shared__ float Ps[64 * 64];
  __shared__ float rel_s[225];
  __shared__ int rid_s[64];

  int tid = threadIdx.x;
  int gw = blockIdx.x;
  int head = blockIdx.y;
  size_t base = ((size_t)gw * 8 + head) * 2048;
  const float4* qg = (const float4*)(g_qkv + base);
  const float4* kg = (const float4*)(g_qkv + (size_t)TOK * CDIM + base);
  const float4* vg = (const float4*)(g_qkv + 2 * (size_t)TOK * CDIM + base);
  ((float4*)qs)[tid] = qg[tid];
  ((float4*)qs)[tid + 256] = qg[tid + 256];
  ((float4*)vs)[tid] = vg[tid];
  ((float4*)vs)[tid + 256] = vg[tid + 256];
#pragma unroll
  for (int it = tid; it < 512; it += 256) {
    float4 kv4 = kg[it];
    int row = it >> 3;
    int c = (it & 7) * 4;
    kT[(c + 0) * 64 + row] = kv4.x;
    kT[(c + 1) * 64 + row] = kv4.y;
    kT[(c + 2) * 64 + row] = kv4.z;
    kT[(c + 3) * 64 + row] = kv4.w;
  }
  if (tid < 225) rel_s[tid] = rel_table[tid * 8 + head];
  if (tid < 64) {
    int nw = gw & 63;
    int h = (nw >> 3) * 8 + (tid >> 3);
    int w = (nw & 7) * 8 + (tid & 7);
    int rh = h < 56 ? 0 : (h < 60 ? 1 : 2);
    int rw = w < 56 ? 0 : (w < 60 ? 1 : 2);
    rid_s[tid] = rh * 3 + rw;
  }
  __syncthreads();

  int r0 = (tid >> 4) * 4;
  int c0 = (tid & 15) * 4;
  float acc[4][4];
#pragma unroll
  for (int u = 0; u < 4; u++)
#pragma unroll
    for (int v = 0; v < 4; v++) acc[u][v] = 0.0f;
#pragma unroll
  for (int kk = 0; kk < 32; kk++) {
    float qr[4];
#pragma unroll
    for (int u = 0; u < 4; u++) qr[u] = qs[(r0 + u) * 32 + kk];
    float4 kv = *(const float4*)&kT[kk * 64 + c0];
    float kr[4] = {kv.x, kv.y, kv.z, kv.w};
#pragma unroll
    for (int u = 0; u < 4; u++)
#pragma unroll
      for (int v = 0; v < 4; v++) acc[u][v] = fmaf(qr[u], kr[v], acc[u][v]);
  }
  const float scale = 0.17677669529663687f;
#pragma unroll
  for (int u = 0; u < 4; u++) {
    int n = r0 + u;
    int in_ = n >> 3, jn = n & 7;
    int ridn = rid_s[n];
    float tmp[4];
#pragma unroll
    for (int v = 0; v < 4; v++) {
      int m = c0 + v;
      int di = in_ - (m >> 3) + 7;
      int dj = jn - (m & 7) + 7;
      float sv = acc[u][v] * scale + rel_s[di * 15 + dj];
      if (ridn != rid_s[m]) sv -= 100.0f;
      tmp[v] = sv;
    }
    *(float4*)&Ps[n * 64 + c0] = make_float4(tmp[0], tmp[1], tmp[2], tmp[3]);
  }
  __syncthreads();

  int warp = tid >> 5, lane = tid & 31;
#pragma unroll
  for (int rr = 0; rr < 8; rr++) {
    int row = warp * 8 + rr;
    float a = Ps[row * 64 + lane];
    float b = Ps[row * 64 + lane + 32];
    float mx = fmaxf(a, b);
#pragma unroll
    for (int o = 16; o; o >>= 1) mx = fmaxf(mx, __shfl_xor_sync(0xffffffffu, mx, o));
    float e1 = __expf(a - mx), e2 = __expf(b - mx);
    float sm = e1 + e2;
#pragma unroll
    for (int o = 16; o; o >>= 1) sm += __shfl_xor_sync(0xffffffffu, sm, o);
    float inv = 1.0f / sm;
    Ps[row * 64 + lane] = e1 * inv;
    Ps[row * 64 + lane + 32] = e2 * inv;
  }
  __syncthreads();

  int row = tid >> 2;
  int db = (tid & 3) * 8;
  float o[8];
#pragma unroll
  for (int u = 0; u < 8; u++) o[u] = 0.0f;
#pragma unroll
  for (int m = 0; m < 64; m++) {
    float p = Ps[row * 64 + m];
    float4 va = *(const float4*)&vs[m * 32 + db];
    float4 vb = *(const float4*)&vs[m * 32 + db + 4];
    o[0] = fmaf(p, va.x, o[0]);
    o[1] = fmaf(p, va.y, o[1]);
    o[2] = fmaf(p, va.z, o[2]);
    o[3] = fmaf(p, va.w, o[3]);
    o[4] = fmaf(p, vb.x, o[4]);
    o[5] = fmaf(p, vb.y, o[5]);
    o[6] = fmaf(p, vb.z, o[6]);
    o[7] = fmaf(p, vb.w, o[7]);
  }
  __nv_bfloat16 h8[8], l8[8];
#pragma unroll
  for (int u = 0; u < 8; u++) split2(o[u], h8[u], l8[u]);
  size_t coff = ((size_t)gw * 64 + row) * 256 + head * 32 + db;
  *(uint4*)(g_ctx_hi + coff) = *(uint4*)h8;
  *(uint4*)(g_ctx_lo + coff) = *(uint4*)l8;
}

// ---------------- host ----------------
extern "C" void kernel_launch(void* const* d_in, const int* in_sizes, int n_in,
                              void* d_out, int out_size) {
  (void)in_sizes; (void)n_in; (void)out_size;
  const float* hs   = (const float*)d_in[0];
  const float* ln1g = (const float*)d_in[1];
  const float* ln1b = (const float*)d_in[2];
  const float* wq   = (const float*)d_in[3];
  const float* bq   = (const float*)d_in[4];
  const float* wk   = (const float*)d_in[5];
  const float* bk   = (const float*)d_in[6];
  const float* wv   = (const float*)d_in[7];
  const float* bv   = (const float*)d_in[8];
  const float* rel  = (const float*)d_in[9];
  const float* wo   = (const float*)d_in[10];
  const float* bo   = (const float*)d_in[11];
  const float* ln2g = (const float*)d_in[12];
  const float* ln2b = (const float*)d_in[13];
  const float* w1   = (const float*)d_in[14];
  const float* b1   = (const float*)d_in[15];
  const float* w2   = (const float*)d_in[16];
  const float* b2   = (const float*)d_in[17];
  float* out = (float*)d_out;

  __nv_bfloat16 *xwh, *xwl, *yh, *yl, *cxh, *cxl, *ith, *itl;
  __nv_bfloat16 *wqkvh, *wqkvl, *woh, *wol, *w1h, *w1l, *w2h, *w2l;
  float *bqkv, *qkv, *hid;
  cudaGetSymbolAddress((void**)&xwh, g_xw_hi);
  cudaGetSymbolAddress((void**)&xwl, g_xw_lo);
  cudaGetSymbolAddress((void**)&yh, g_y_hi);
  cudaGetSymbolAddress((void**)&yl, g_y_lo);
  cudaGetSymbolAddress((void**)&cxh, g_ctx_hi);
  cudaGetSymbolAddress((void**)&cxl, g_ctx_lo);
  cudaGetSymbolAddress((void**)&ith, g_int_hi);
  cudaGetSymbolAddress((void**)&itl, g_int_lo);
  cudaGetSymbolAddress((void**)&wqkvh, g_wqkv_hi);
  cudaGetSymbolAddress((void**)&wqkvl, g_wqkv_lo);
  cudaGetSymbolAddress((void**)&woh, g_wo_hi);
  cudaGetSymbolAddress((void**)&wol, g_wo_lo);
  cudaGetSymbolAddress((void**)&w1h, g_w1_hi);
  cudaGetSymbolAddress((void**)&w1l, g_w1_lo);
  cudaGetSymbolAddress((void**)&w2h, g_w2_hi);
  cudaGetSymbolAddress((void**)&w2l, g_w2_lo);
  cudaGetSymbolAddress((void**)&bqkv, g_bqkv);
  cudaGetSymbolAddress((void**)&qkv, g_qkv);
  cudaGetSymbolAddress((void**)&hid, g_hidden);

  const int SMSZ = 2 * 40960;
  cudaFuncSetAttribute(gemm_mma<0>, cudaFuncAttributeMaxDynamicSharedMemorySize, SMSZ);
  cudaFuncSetAttribute(gemm_mma<1>, cudaFuncAttributeMaxDynamicSharedMemorySize, SMSZ);
  cudaFuncSetAttribute(gemm_mma<2>, cudaFuncAttributeMaxDynamicSharedMemorySize, SMSZ);
  cudaFuncSetAttribute(gemm_mma<3>, cudaFuncAttributeMaxDynamicSharedMemorySize, SMSZ);

  // weight prep
  split_w<<<256, 256>>>(wq, wqkvh, wqkvl, 65536);
  split_w<<<256, 256>>>(wk, wqkvh + 65536, wqkvl + 65536, 65536);
  split_w<<<256, 256>>>(wv, wqkvh + 131072, wqkvl + 131072, 65536);
  split_w<<<256, 256>>>(wo, woh, wol, 65536);
  split_w<<<1024, 256>>>(w1, w1h, w1l, 262144);
  split_w<<<1024, 256>>>(w2, w2h, w2l, 262144);
  concat_bias<<<3, 256>>>(bq, bk, bv);

  ln_split<true><<<4096, 256>>>(hs, ln1g, ln1b, xwh, xwl);

  gemm_mma<0><<<dim3(6, 256), 256, SMSZ>>>(xwh, xwl, wqkvh, wqkvl, bqkv, qkv,
                                           nullptr, nullptr, nullptr, 256);

  attn_kernel<<<dim3(512, 8), 256>>>(rel);

  gemm_mma<1><<<dim3(2, 256), 256, SMSZ>>>(cxh, cxl, woh, wol, bo, hid,
                                           nullptr, nullptr, hs, 256);

  ln_split<false><<<4096, 256>>>(hid, ln2g, ln2b, yh, yl);

  gemm_mma<2><<<dim3(8, 256), 256, SMSZ>>>(yh, yl, w1h, w1l, b1, nullptr,
                                           ith, itl, nullptr, 256);

  gemm_mma<3><<<dim3(2, 256), 256, SMSZ>>>(ith, itl, w2h, w2l, b2, out,
                                           nullptr, nullptr, hid, 1024);
}

// round 4
// speedup vs baseline: 3.6879x; 2.0179x over previous
#include <cuda_runtime.h>
#include <cuda_fp16.h>
#include <math.h>
#include <stdint.h>

#define TOK 32768
#define CDIM 256
#define MLPD 1024

// ---------------- device scratch ----------------
__device__ __half g_x_h[TOK * CDIM];        // LN1 output (windowed order)
__device__ __half g_y_h[TOK * CDIM];        // LN2 output
__device__ __half g_ctx_h[TOK * CDIM];      // attention context (windowed order)
__device__ __half g_int_h[TOK * MLPD];      // MLP hidden
__device__ __half g_wqkv_h[3 * CDIM * CDIM];
__device__ __half g_wo_h[CDIM * CDIM];
__device__ __half g_w1_h[MLPD * CDIM];
__device__ __half g_w2_h[CDIM * MLPD];
__device__ float g_bqkv[3 * CDIM];
__device__ __half g_qkv[3 * TOK * CDIM];    // [sel][win][head][n][d]
__device__ float g_hidden[TOK * CDIM];

// ---------------- helpers ----------------
__device__ __forceinline__ uint32_t smem_u32(const void* p) {
  uint32_t a;
  asm("{ .reg .u64 t; cvta.to.shared.u64 t, %1; cvt.u32.u64 %0, t; }"
      : "=r"(a) : "l"(p));
  return a;
}

#define LDSM4(r, addr) \
  asm volatile("ldmatrix.sync.aligned.m8n8.x4.shared.b16 {%0,%1,%2,%3}, [%4];" \
               : "=r"((r)[0]), "=r"((r)[1]), "=r"((r)[2]), "=r"((r)[3]) \
               : "r"(addr))

#define MMA16816(d, a, b0, b1) \
  asm volatile( \
      "mma.sync.aligned.m16n8k16.row.col.f32.f16.f16.f32 " \
      "{%0,%1,%2,%3}, {%4,%5,%6,%7}, {%8,%9}, {%0,%1,%2,%3};" \
      : "+f"((d)[0]), "+f"((d)[1]), "+f"((d)[2]), "+f"((d)[3]) \
      : "r"((a)[0]), "r"((a)[1]), "r"((a)[2]), "r"((a)[3]), \
        "r"(b0), "r"(b1))

// windowed token index -> original token index (+4 cyclic shift)
__device__ __forceinline__ int map_shift(int t) {
  int b = t >> 12, rr = t & 4095;
  int win = rr >> 6, n = rr & 63;
  int wh = win >> 3, ww = win & 7, i = n >> 3, j = n & 7;
  int h = (wh * 8 + i + 4) & 63;
  int w = (ww * 8 + j + 4) & 63;
  return (b << 12) + (h << 6) + w;
}

// ---------------- LayerNorm -> fp16 (one warp per token) -------------------
template <bool GATHER>
__global__ void __launch_bounds__(256) ln_h(
    const float* __restrict__ x, const float* __restrict__ gam,
    const float* __restrict__ bet, __half* __restrict__ oh) {
  int warp = threadIdx.x >> 5, lane = threadIdx.x & 31;
  int t = blockIdx.x * 8 + warp;
  int src = GATHER ? map_shift(t) : t;
  const float4* xr = (const float4*)(x + (size_t)src * CDIM);
  float4 v0 = xr[lane], v1 = xr[lane + 32];
  float s = v0.x + v0.y + v0.z + v0.w + v1.x + v1.y + v1.z + v1.w;
  float q = v0.x * v0.x + v0.y * v0.y + v0.z * v0.z + v0.w * v0.w +
            v1.x * v1.x + v1.y * v1.y + v1.z * v1.z + v1.w * v1.w;
#pragma unroll
  for (int o = 16; o; o >>= 1) {
    s += __shfl_xor_sync(0xffffffffu, s, o);
    q += __shfl_xor_sync(0xffffffffu, q, o);
  }
  float mean = s * (1.0f / 256.0f);
  float var = q * (1.0f / 256.0f) - mean * mean;
  float rs = rsqrtf(var + 1e-5f);
  const float4* g4 = (const float4*)gam;
  const float4* b4 = (const float4*)bet;
  __half h[4];
  {
    float4 ga = g4[lane], be = b4[lane];
    h[0] = __float2half((v0.x - mean) * rs * ga.x + be.x);
    h[1] = __float2half((v0.y - mean) * rs * ga.y + be.y);
    h[2] = __float2half((v0.z - mean) * rs * ga.z + be.z);
    h[3] = __float2half((v0.w - mean) * rs * ga.w + be.w);
    *(uint2*)(oh + (size_t)t * CDIM + lane * 4) = *(uint2*)h;
  }
  {
    float4 ga = g4[lane + 32], be = b4[lane + 32];
    h[0] = __float2half((v1.x - mean) * rs * ga.x + be.x);
    h[1] = __float2half((v1.y - mean) * rs * ga.y + be.y);
    h[2] = __float2half((v1.z - mean) * rs * ga.z + be.z);
    h[3] = __float2half((v1.w - mean) * rs * ga.w + be.w);
    *(uint2*)(oh + (size_t)t * CDIM + 128 + lane * 4) = *(uint2*)h;
  }
}

// ---------------- weight convert / bias concat ----------------
__global__ void conv_w(const float* __restrict__ src, __half* __restrict__ dst, int n) {
  int i = blockIdx.x * 256 + threadIdx.x;
  if (i < n) dst[i] = __float2half(src[i]);
}

__global__ void concat_bias(const float* __restrict__ a, const float* __restrict__ b,
                            const float* __restrict__ c) {
  int i = blockIdx.x * 256 + threadIdx.x;
  if (i < 256) g_bqkv[i] = a[i];
  else if (i < 512) g_bqkv[i] = b[i - 256];
  else if (i < 768) g_bqkv[i] = c[i - 512];
}

// ---------------- HMMA fp16 GEMM: out = A @ W^T (+bias, epilogue) ----------
// A: [M][K] fp16 row-major, B(W): [Ntot][K] fp16 row-major.
// CTA tile 128x128, K-slab 32, double-buffered SMEM (80B row stride),
// warp tile 64x32, mma.sync m16n8k16 single pass.
// EPI 0: QKV fp16 permute  1: WO scatter+residual  2: GELU->fp16  3: +residual
template <int EPI>
__global__ void __launch_bounds__(256, 2) gemm_mma(
    const __half* __restrict__ A, const __half* __restrict__ B,
    const float* __restrict__ bias, float* __restrict__ out,
    __half* __restrict__ out_h, const float* __restrict__ extra, int K) {
  extern __shared__ char smraw[];
  const int STG = 20480;  // 2 arrays * 128 rows * 80 B
  int tid = threadIdx.x, wid = tid >> 5, lane = tid & 31;
  int warp_row = wid >> 2, warp_col = wid & 3;
  int row0 = blockIdx.y * 128, col0 = blockIdx.x * 128;
  uint32_t smem_base = smem_u32(smraw);

  float acc[4][4][4];
#pragma unroll
  for (int mi = 0; mi < 4; mi++)
#pragma unroll
    for (int ni = 0; ni < 4; ni++)
#pragma unroll
      for (int u = 0; u < 4; u++) acc[mi][ni][u] = 0.0f;

  int lrow = tid >> 2;   // 0..63
  int lchunk = tid & 3;  // 16B chunk within 64B k-slab row

  int nslabs = K >> 5;
  uint4 ra[2], rc[2];

  int a_r = warp_row * 64 + (lane & 15);
  int b_r = warp_col * 32 + (lane & 15);
  int oct = lane >> 4;

  // prefetch slab 0
#pragma unroll
  for (int r = 0; r < 2; r++) {
    int row = lrow + r * 64;
    ra[r] = *(const uint4*)(A + (size_t)(row0 + row) * K + lchunk * 8);
    rc[r] = *(const uint4*)(B + (size_t)(col0 + row) * K + lchunk * 8);
  }

  for (int s = 0; s < nslabs; s++) {
    int buf = s & 1;
    {
      char* base = smraw + buf * STG;
#pragma unroll
      for (int r = 0; r < 2; r++) {
        uint32_t off = (lrow + r * 64) * 80 + lchunk * 16;
        *(uint4*)(base + off) = ra[r];
        *(uint4*)(base + 10240 + off) = rc[r];
      }
    }
    if (s + 1 < nslabs) {
      int k0 = (s + 1) * 32;
#pragma unroll
      for (int r = 0; r < 2; r++) {
        int row = lrow + r * 64;
        ra[r] = *(const uint4*)(A + (size_t)(row0 + row) * K + k0 + lchunk * 8);
        rc[r] = *(const uint4*)(B + (size_t)(col0 + row) * K + k0 + lchunk * 8);
      }
    }
    __syncthreads();
    uint32_t st = smem_base + buf * STG;
#pragma unroll
    for (int kk = 0; kk < 2; kk++) {
      uint32_t ah[4][4];
#pragma unroll
      for (int mi = 0; mi < 4; mi++) {
        uint32_t addr = st + (a_r + mi * 16) * 80 + (2 * kk + oct) * 16;
        LDSM4(ah[mi], addr);
      }
      uint32_t bh[2][4];
#pragma unroll
      for (int nb = 0; nb < 2; nb++) {
        uint32_t addr = st + 10240 + (b_r + nb * 16) * 80 + (2 * kk + oct) * 16;
        LDSM4(bh[nb], addr);
      }
#pragma unroll
      for (int mi = 0; mi < 4; mi++)
#pragma unroll
        for (int ni = 0; ni < 4; ni++) {
          int nb = ni >> 1, up = ni & 1;
          MMA16816(acc[mi][ni], ah[mi], bh[nb][up], bh[nb][up + 2]);
        }
    }
    __syncthreads();
  }

  // ---------------- epilogue ----------------
  int group = lane >> 2, tig = lane & 3;
#pragma unroll
  for (int mi = 0; mi < 4; mi++) {
#pragma unroll
    for (int half = 0; half < 2; half++) {
      int r = row0 + warp_row * 64 + mi * 16 + group + 8 * half;
      if (EPI == 0) {
        int win = r >> 6, n = r & 63;
#pragma unroll
        for (int ni = 0; ni < 4; ni++) {
          int c = col0 + warp_col * 32 + ni * 8 + tig * 2;
          int sel = c >> 8, cw = c & 255;
          int head = cw >> 5, d = cw & 31;
          float2 bb = *(const float2*)(bias + c);
          __half2 v;
          v.x = __float2half(acc[mi][ni][2 * half + 0] + bb.x);
          v.y = __float2half(acc[mi][ni][2 * half + 1] + bb.y);
          *(__half2*)(g_qkv + (size_t)sel * (TOK * CDIM) + (size_t)win * 16384 +
                      head * 2048 + n * 32 + d) = v;
        }
      } else if (EPI == 1) {
        int dst = map_shift(r);
#pragma unroll
        for (int ni = 0; ni < 4; ni++) {
          int c = col0 + warp_col * 32 + ni * 8 + tig * 2;
          size_t off = (size_t)dst * 256 + c;
          float2 bb = *(const float2*)(bias + c);
          float2 ex = *(const float2*)(extra + off);
          float2 v;
          v.x = acc[mi][ni][2 * half + 0] + bb.x + ex.x;
          v.y = acc[mi][ni][2 * half + 1] + bb.y + ex.y;
          *(float2*)(out + off) = v;
        }
      } else if (EPI == 2) {
#pragma unroll
        for (int ni = 0; ni < 4; ni++) {
          int c = col0 + warp_col * 32 + ni * 8 + tig * 2;
          size_t off = (size_t)r * MLPD + c;
          float2 bb = *(const float2*)(bias + c);
          float v0 = acc[mi][ni][2 * half + 0] + bb.x;
          float v1 = acc[mi][ni][2 * half + 1] + bb.y;
          v0 = 0.5f * v0 * (1.0f + erff(v0 * 0.7071067811865476f));
          v1 = 0.5f * v1 * (1.0f + erff(v1 * 0.7071067811865476f));
          __half2 hh;
          hh.x = __float2half(v0);
          hh.y = __float2half(v1);
          *(__half2*)(out_h + off) = hh;
        }
      } else {
#pragma unroll
        for (int ni = 0; ni < 4; ni++) {
          int c = col0 + warp_col * 32 + ni * 8 + tig * 2;
          size_t off = (size_t)r * 256 + c;
          float2 bb = *(const float2*)(bias + c);
          float2 ex = *(const float2*)(extra + off);
          float2 v;
          v.x = acc[mi][ni][2 * half + 0] + bb.x + ex.x;
          v.y = acc[mi][ni][2 * half + 1] + bb.y + ex.y;
          *(float2*)(out + off) = v;
        }
      }
    }
  }
}

// ---------------- windowed attention: one block per (window, head) ---------
__global__ void __launch_bounds__(256) attn_kernel(
    const float* __restrict__ rel_table) {
  __shared__ float qs[64 * 32];
  __shared__ float kT[32 * 64];
  __shared__ float vs[64 * 32];
  __shared__ float Ps[64 * 64];
  __shared__ float rel_s[225];
  __shared__ int rid_s[64];

  int tid = threadIdx.x;
  int gw = blockIdx.x;
  int head = blockIdx.y;
  size_t base = ((size_t)gw * 8 + head) * 2048;
  const __half* qg = g_qkv + base;
  const __half* kg = g_qkv + (size_t)TOK * CDIM + base;
  const __half* vg = g_qkv + 2 * (size_t)TOK * CDIM + base;

  // each thread handles one 8-half chunk (2048 elems / 8 = 256 chunks)
  {
    int e = tid * 8;
    uint4 qa = *(const uint4*)(qg + e);
    uint4 va = *(const uint4*)(vg + e);
    const __half* qh = (const __half*)&qa;
    const __half* vh = (const __half*)&va;
#pragma unroll
    for (int u = 0; u < 8; u++) {
      qs[e + u] = __half2float(qh[u]);
      vs[e + u] = __half2float(vh[u]);
    }
    uint4 ka = *(const uint4*)(kg + e);
    const __half* kh = (const __half*)&ka;
    int row = e >> 5, c0 = e & 31;
#pragma unroll
    for (int u = 0; u < 8; u++) kT[(c0 + u) * 64 + row] = __half2float(kh[u]);
  }
  if (tid < 225) rel_s[tid] = rel_table[tid * 8 + head];
  if (tid < 64) {
    int nw = gw & 63;
    int h = (nw >> 3) * 8 + (tid >> 3);
    int w = (nw & 7) * 8 + (tid & 7);
    int rh = h < 56 ? 0 : (h < 60 ? 1 : 2);
    int rw = w < 56 ? 0 : (w < 60 ? 1 : 2);
    rid_s[tid] = rh * 3 + rw;
  }
  __syncthreads();

  int r0 = (tid >> 4) * 4;
  int c0 = (tid & 15) * 4;
  float acc[4][4];
#pragma unroll
  for (int u = 0; u < 4; u++)
#pragma unroll
    for (int v = 0; v < 4; v++) acc[u][v] = 0.0f;
#pragma unroll
  for (int kk = 0; kk < 32; kk++) {
    float qr[4];
#pragma unroll
    for (int u = 0; u < 4; u++) qr[u] = qs[(r0 + u) * 32 + kk];
    float4 kv = *(const float4*)&kT[kk * 64 + c0];
    float kr[4] = {kv.x, kv.y, kv.z, kv.w};
#pragma unroll
    for (int u = 0; u < 4; u++)
#pragma unroll
      for (int v = 0; v < 4; v++) acc[u][v] = fmaf(qr[u], kr[v], acc[u][v]);
  }
  const float scale = 0.17677669529663687f;
#pragma unroll
  for (int u = 0; u < 4; u++) {
    int n = r0 + u;
    int in_ = n >> 3, jn = n & 7;
    int ridn = rid_s[n];
    float tmp[4];
#pragma unroll
    for (int v = 0; v < 4; v++) {
      int m = c0 + v;
      int di = in_ - (m >> 3) + 7;
      int dj = jn - (m & 7) + 7;
      float sv = acc[u][v] * scale + rel_s[di * 15 + dj];
      if (ridn != rid_s[m]) sv -= 100.0f;
      tmp[v] = sv;
    }
    *(float4*)&Ps[n * 64 + c0] = make_float4(tmp[0], tmp[1], tmp[2], tmp[3]);
  }
  __syncthreads();

  int warp = tid >> 5, lane = tid & 31;
#pragma unroll
  for (int rr = 0; rr < 8; rr++) {
    int row = warp * 8 + rr;
    float a = Ps[row * 64 + lane];
    float b = Ps[row * 64 + lane + 32];
    float mx = fmaxf(a, b);
#pragma unroll
    for (int o = 16; o; o >>= 1) mx = fmaxf(mx, __shfl_xor_sync(0xffffffffu, mx, o));
    float e1 = __expf(a - mx), e2 = __expf(b - mx);
    float sm = e1 + e2;
#pragma unroll
    for (int o = 16; o; o >>= 1) sm += __shfl_xor_sync(0xffffffffu, sm, o);
    float inv = 1.0f / sm;
    Ps[row * 64 + lane] = e1 * inv;
    Ps[row * 64 + lane + 32] = e2 * inv;
  }
  __syncthreads();

  int row = tid >> 2;
  int db = (tid & 3) * 8;
  float o[8];
#pragma unroll
  for (int u = 0; u < 8; u++) o[u] = 0.0f;
#pragma unroll
  for (int m = 0; m < 64; m++) {
    float p = Ps[row * 64 + m];
    float4 va = *(const float4*)&vs[m * 32 + db];
    float4 vb = *(const float4*)&vs[m * 32 + db + 4];
    o[0] = fmaf(p, va.x, o[0]);
    o[1] = fmaf(p, va.y, o[1]);
    o[2] = fmaf(p, va.z, o[2]);
    o[3] = fmaf(p, va.w, o[3]);
    o[4] = fmaf(p, vb.x, o[4]);
    o[5] = fmaf(p, vb.y, o[5]);
    o[6] = fmaf(p, vb.z, o[6]);
    o[7] = fmaf(p, vb.w, o[7]);
  }
  __half h8[8];
#pragma unroll
  for (int u = 0; u < 8; u++) h8[u] = __float2half(o[u]);
  *(uint4*)(g_ctx_h + ((size_t)gw * 64 + row) * 256 + head * 32 + db) = *(uint4*)h8;
}

// ---------------- host ----------------
extern "C" void kernel_launch(void* const* d_in, const int* in_sizes, int n_in,
                              void* d_out, int out_size) {
  (void)in_sizes; (void)n_in; (void)out_size;
  const float* hs   = (const float*)d_in[0];
  const float* ln1g = (const float*)d_in[1];
  const float* ln1b = (const float*)d_in[2];
  const float* wq   = (const float*)d_in[3];
  const float* bq   = (const float*)d_in[4];
  const float* wk   = (const float*)d_in[5];
  const float* bk   = (const float*)d_in[6];
  const float* wv   = (const float*)d_in[7];
  const float* bv   = (const float*)d_in[8];
  const float* rel  = (const float*)d_in[9];
  const float* wo   = (const float*)d_in[10];
  const float* bo   = (const float*)d_in[11];
  const float* ln2g = (const float*)d_in[12];
  const float* ln2b = (const float*)d_in[13];
  const float* w1   = (const float*)d_in[14];
  const float* b1   = (const float*)d_in[15];
  const float* w2   = (const float*)d_in[16];
  const float* b2   = (const float*)d_in[17];
  float* out = (float*)d_out;

  __half *xh, *yh, *cxh, *ith, *wqkvh, *woh, *w1h, *w2h;
  float *bqkv, *hid;
  cudaGetSymbolAddress((void**)&xh, g_x_h);
  cudaGetSymbolAddress((void**)&yh, g_y_h);
  cudaGetSymbolAddress((void**)&cxh, g_ctx_h);
  cudaGetSymbolAddress((void**)&ith, g_int_h);
  cudaGetSymbolAddress((void**)&wqkvh, g_wqkv_h);
  cudaGetSymbolAddress((void**)&woh, g_wo_h);
  cudaGetSymbolAddress((void**)&w1h, g_w1_h);
  cudaGetSymbolAddress((void**)&w2h, g_w2_h);
  cudaGetSymbolAddress((void**)&bqkv, g_bqkv);
  cudaGetSymbolAddress((void**)&hid, g_hidden);

  const int SMSZ = 2 * 20480;
  cudaFuncSetAttribute(gemm_mma<0>, cudaFuncAttributeMaxDynamicSharedMemorySize, SMSZ);
  cudaFuncSetAttribute(gemm_mma<1>, cudaFuncAttributeMaxDynamicSharedMemorySize, SMSZ);
  cudaFuncSetAttribute(gemm_mma<2>, cudaFuncAttributeMaxDynamicSharedMemorySize, SMSZ);
  cudaFuncSetAttribute(gemm_mma<3>, cudaFuncAttributeMaxDynamicSharedMemorySize, SMSZ);

  conv_w<<<256, 256>>>(wq, wqkvh, 65536);
  conv_w<<<256, 256>>>(wk, wqkvh + 65536, 65536);
  conv_w<<<256, 256>>>(wv, wqkvh + 131072, 65536);
  conv_w<<<256, 256>>>(wo, woh, 65536);
  conv_w<<<1024, 256>>>(w1, w1h, 262144);
  conv_w<<<1024, 256>>>(w2, w2h, 262144);
  concat_bias<<<3, 256>>>(bq, bk, bv);

  ln_h<true><<<4096, 256>>>(hs, ln1g, ln1b, xh);

  gemm_mma<0><<<dim3(6, 256), 256, SMSZ>>>(xh, wqkvh, bqkv, nullptr, nullptr,
                                           nullptr, 256);

  attn_kernel<<<dim3(512, 8), 256>>>(rel);

  gemm_mma<1><<<dim3(2, 256), 256, SMSZ>>>(cxh, woh, bo, hid, nullptr, hs, 256);

  ln_h<false><<<4096, 256>>>(hid, ln2g, ln2b, yh);

  gemm_mma<2><<<dim3(8, 256), 256, SMSZ>>>(yh, w1h, b1, nullptr, ith, nullptr, 256);

  gemm_mma<3><<<dim3(2, 256), 256, SMSZ>>>(ith, w2h, b2, out, nullptr, hid, 1024);
}

// round 5
// speedup vs baseline: 4.0077x; 1.0867x over previous
#include <cuda_runtime.h>
#include <cuda_fp16.h>
#include <math.h>
#include <stdint.h>

#define TOK 32768
#define CDIM 256
#define MLPD 1024

// ---------------- device scratch ----------------
__device__ __half g_x_h[TOK * CDIM];        // LN1 output (windowed order)
__device__ __half g_y_h[TOK * CDIM];        // LN2 output
__device__ __half g_ctx_h[TOK * CDIM];      // attention context (windowed order)
__device__ __half g_int_h[TOK * MLPD];      // MLP hidden
__device__ __half g_wqkv_h[3 * CDIM * CDIM];
__device__ __half g_wo_h[CDIM * CDIM];
__device__ __half g_w1_h[MLPD * CDIM];
__device__ __half g_w2_h[CDIM * MLPD];
__device__ float g_bqkv[3 * CDIM];
__device__ __half g_qkv[3 * TOK * CDIM];    // [sel][win][head][n][d]
__device__ float g_hidden[TOK * CDIM];

// ---------------- helpers ----------------
__device__ __forceinline__ uint32_t smem_u32(const void* p) {
  uint32_t a;
  asm("{ .reg .u64 t; cvta.to.shared.u64 t, %1; cvt.u32.u64 %0, t; }"
      : "=r"(a) : "l"(p));
  return a;
}

__device__ __forceinline__ void cp16(uint32_t smem, const void* g) {
  asm volatile("cp.async.cg.shared.global [%0], [%1], 16;" :: "r"(smem), "l"(g));
}
#define CP_COMMIT() asm volatile("cp.async.commit_group;" ::: "memory")
#define CP_WAIT2() asm volatile("cp.async.wait_group 2;" ::: "memory")

#define LDSM4(r, addr) \
  asm volatile("ldmatrix.sync.aligned.m8n8.x4.shared.b16 {%0,%1,%2,%3}, [%4];" \
               : "=r"((r)[0]), "=r"((r)[1]), "=r"((r)[2]), "=r"((r)[3]) \
               : "r"(addr))

#define MMA16816(d, a, b0, b1) \
  asm volatile( \
      "mma.sync.aligned.m16n8k16.row.col.f32.f16.f16.f32 " \
      "{%0,%1,%2,%3}, {%4,%5,%6,%7}, {%8,%9}, {%0,%1,%2,%3};" \
      : "+f"((d)[0]), "+f"((d)[1]), "+f"((d)[2]), "+f"((d)[3]) \
      : "r"((a)[0]), "r"((a)[1]), "r"((a)[2]), "r"((a)[3]), \
        "r"(b0), "r"(b1))

// windowed token index -> original token index (+4 cyclic shift)
__device__ __forceinline__ int map_shift(int t) {
  int b = t >> 12, rr = t & 4095;
  int win = rr >> 6, n = rr & 63;
  int wh = win >> 3, ww = win & 7, i = n >> 3, j = n & 7;
  int h = (wh * 8 + i + 4) & 63;
  int w = (ww * 8 + j + 4) & 63;
  return (b << 12) + (h << 6) + w;
}

// ---------------- LayerNorm -> fp16 (one warp per token) -------------------
template <bool GATHER>
__global__ void __launch_bounds__(256) ln_h(
    const float* __restrict__ x, const float* __restrict__ gam,
    const float* __restrict__ bet, __half* __restrict__ oh) {
  int warp = threadIdx.x >> 5, lane = threadIdx.x & 31;
  int t = blockIdx.x * 8 + warp;
  int src = GATHER ? map_shift(t) : t;
  const float4* xr = (const float4*)(x + (size_t)src * CDIM);
  float4 v0 = xr[lane], v1 = xr[lane + 32];
  float s = v0.x + v0.y + v0.z + v0.w + v1.x + v1.y + v1.z + v1.w;
  float q = v0.x * v0.x + v0.y * v0.y + v0.z * v0.z + v0.w * v0.w +
            v1.x * v1.x + v1.y * v1.y + v1.z * v1.z + v1.w * v1.w;
#pragma unroll
  for (int o = 16; o; o >>= 1) {
    s += __shfl_xor_sync(0xffffffffu, s, o);
    q += __shfl_xor_sync(0xffffffffu, q, o);
  }
  float mean = s * (1.0f / 256.0f);
  float var = q * (1.0f / 256.0f) - mean * mean;
  float rs = rsqrtf(var + 1e-5f);
  const float4* g4 = (const float4*)gam;
  const float4* b4 = (const float4*)bet;
  __half h[4];
  {
    float4 ga = g4[lane], be = b4[lane];
    h[0] = __float2half((v0.x - mean) * rs * ga.x + be.x);
    h[1] = __float2half((v0.y - mean) * rs * ga.y + be.y);
    h[2] = __float2half((v0.z - mean) * rs * ga.z + be.z);
    h[3] = __float2half((v0.w - mean) * rs * ga.w + be.w);
    *(uint2*)(oh + (size_t)t * CDIM + lane * 4) = *(uint2*)h;
  }
  {
    float4 ga = g4[lane + 32], be = b4[lane + 32];
    h[0] = __float2half((v1.x - mean) * rs * ga.x + be.x);
    h[1] = __float2half((v1.y - mean) * rs * ga.y + be.y);
    h[2] = __float2half((v1.z - mean) * rs * ga.z + be.z);
    h[3] = __float2half((v1.w - mean) * rs * ga.w + be.w);
    *(uint2*)(oh + (size_t)t * CDIM + 128 + lane * 4) = *(uint2*)h;
  }
}

// ---------------- merged weight prep: one launch -------------------------
// float4-vectorized fp32->fp16 for wq|wk|wv|wo|w1|w2 + bias concat.
__global__ void __launch_bounds__(256) prep_weights(
    const float* __restrict__ wq, const float* __restrict__ wk,
    const float* __restrict__ wv, const float* __restrict__ wo,
    const float* __restrict__ w1, const float* __restrict__ w2,
    const float* __restrict__ bq, const float* __restrict__ bk,
    const float* __restrict__ bv) {
  int j = blockIdx.x * 256 + threadIdx.x;  // float4 index, total 196608
  const float* src;
  __half* dst;
  int loc;
  if (j < 16384) { src = wq; dst = g_wqkv_h; loc = j; }
  else if (j < 32768) { src = wk; dst = g_wqkv_h + 65536; loc = j - 16384; }
  else if (j < 49152) { src = wv; dst = g_wqkv_h + 131072; loc = j - 32768; }
  else if (j < 65536) { src = wo; dst = g_wo_h; loc = j - 49152; }
  else if (j < 131072) { src = w1; dst = g_w1_h; loc = j - 65536; }
  else { src = w2; dst = g_w2_h; loc = j - 131072; }
  float4 v = ((const float4*)src)[loc];
  __half h[4];
  h[0] = __float2half(v.x);
  h[1] = __float2half(v.y);
  h[2] = __float2half(v.z);
  h[3] = __float2half(v.w);
  *(uint2*)(dst + loc * 4) = *(uint2*)h;
  int g = j;  // reuse first 768 threads for bias
  if (g < 256) g_bqkv[g] = bq[g];
  else if (g < 512) g_bqkv[g] = bk[g - 256];
  else if (g < 768) g_bqkv[g] = bv[g - 512];
}

// ---------------- HMMA fp16 GEMM, cp.async 4-stage pipeline ----------------
// A: [M][K] fp16 row-major, B(W): [Ntot][K] fp16 row-major.
// CTA tile 128x128, K-slab 32, 4-stage cp.async, warp tile 64x32.
// EPI 0: QKV fp16 permute  1: WO scatter+residual  2: GELU->fp16  3: +residual
template <int EPI>
__global__ void __launch_bounds__(256, 2) gemm_mma(
    const __half* __restrict__ A, const __half* __restrict__ B,
    const float* __restrict__ bias, float* __restrict__ out,
    __half* __restrict__ out_h, const float* __restrict__ extra, int K) {
  extern __shared__ char smraw[];
  const int STG = 20480;  // per stage: A 128*80 + B 128*80
  int tid = threadIdx.x, wid = tid >> 5, lane = tid & 31;
  int warp_row = wid >> 2, warp_col = wid & 3;
  int row0 = blockIdx.y * 128, col0 = blockIdx.x * 128;
  uint32_t sm = smem_u32(smraw);

  float acc[4][4][4];
#pragma unroll
  for (int mi = 0; mi < 4; mi++)
#pragma unroll
    for (int ni = 0; ni < 4; ni++)
#pragma unroll
      for (int u = 0; u < 4; u++) acc[mi][ni][u] = 0.0f;

  int lrow = tid >> 2;   // 0..63
  int lchunk = tid & 3;  // 16B chunk within 64B k-slab row
  int nslabs = K >> 5;

  const __half* Ab = A + (size_t)row0 * K + lchunk * 8;
  const __half* Bb = B + (size_t)col0 * K + lchunk * 8;
  uint32_t soff = lrow * 80 + lchunk * 16;

  // prologue: stages 0..2
#pragma unroll
  for (int p = 0; p < 3; p++) {
    uint32_t st = sm + p * STG;
    int k0 = p * 32;
#pragma unroll
    for (int r = 0; r < 2; r++) {
      int row = lrow + r * 64;
      cp16(st + soff + r * 64 * 80, Ab + (size_t)row * K + k0);
      cp16(st + 10240 + soff + r * 64 * 80, Bb + (size_t)row * K + k0);
    }
    CP_COMMIT();
  }

  int a_r = warp_row * 64 + (lane & 15);
  int b_r = warp_col * 32 + (lane & 15);
  int oct = lane >> 4;

  for (int s = 0; s < nslabs; s++) {
    CP_WAIT2();
    __syncthreads();
    // issue slab s+3 into slot (s+3)&3 (overwrites slot computed in iter s-1)
    if (s + 3 < nslabs) {
      uint32_t st = sm + ((s + 3) & 3) * STG;
      int k0 = (s + 3) * 32;
#pragma unroll
      for (int r = 0; r < 2; r++) {
        int row = lrow + r * 64;
        cp16(st + soff + r * 64 * 80, Ab + (size_t)row * K + k0);
        cp16(st + 10240 + soff + r * 64 * 80, Bb + (size_t)row * K + k0);
      }
    }
    CP_COMMIT();

    uint32_t st = sm + (s & 3) * STG;
#pragma unroll
    for (int kk = 0; kk < 2; kk++) {
      uint32_t ah[4][4];
#pragma unroll
      for (int mi = 0; mi < 4; mi++) {
        uint32_t addr = st + (a_r + mi * 16) * 80 + (2 * kk + oct) * 16;
        LDSM4(ah[mi], addr);
      }
      uint32_t bh[2][4];
#pragma unroll
      for (int nb = 0; nb < 2; nb++) {
        uint32_t addr = st + 10240 + (b_r + nb * 16) * 80 + (2 * kk + oct) * 16;
        LDSM4(bh[nb], addr);
      }
#pragma unroll
      for (int mi = 0; mi < 4; mi++)
#pragma unroll
        for (int ni = 0; ni < 4; ni++) {
          int nb = ni >> 1, up = ni & 1;
          MMA16816(acc[mi][ni], ah[mi], bh[nb][up], bh[nb][up + 2]);
        }
    }
  }

  // ---------------- epilogue ----------------
  int group = lane >> 2, tig = lane & 3;
#pragma unroll
  for (int mi = 0; mi < 4; mi++) {
#pragma unroll
    for (int half = 0; half < 2; half++) {
      int r = row0 + warp_row * 64 + mi * 16 + group + 8 * half;
      if (EPI == 0) {
        int win = r >> 6, n = r & 63;
#pragma unroll
        for (int ni = 0; ni < 4; ni++) {
          int c = col0 + warp_col * 32 + ni * 8 + tig * 2;
          int sel = c >> 8, cw = c & 255;
          int head = cw >> 5, d = cw & 31;
          float2 bb = *(const float2*)(bias + c);
          __half2 v;
          v.x = __float2half(acc[mi][ni][2 * half + 0] + bb.x);
          v.y = __float2half(acc[mi][ni][2 * half + 1] + bb.y);
          *(__half2*)(g_qkv + (size_t)sel * (TOK * CDIM) + (size_t)win * 16384 +
                      head * 2048 + n * 32 + d) = v;
        }
      } else if (EPI == 1) {
        int dst = map_shift(r);
#pragma unroll
        for (int ni = 0; ni < 4; ni++) {
          int c = col0 + warp_col * 32 + ni * 8 + tig * 2;
          size_t off = (size_t)dst * 256 + c;
          float2 bb = *(const float2*)(bias + c);
          float2 ex = *(const float2*)(extra + off);
          float2 v;
          v.x = acc[mi][ni][2 * half + 0] + bb.x + ex.x;
          v.y = acc[mi][ni][2 * half + 1] + bb.y + ex.y;
          *(float2*)(out + off) = v;
        }
      } else if (EPI == 2) {
#pragma unroll
        for (int ni = 0; ni < 4; ni++) {
          int c = col0 + warp_col * 32 + ni * 8 + tig * 2;
          size_t off = (size_t)r * MLPD + c;
          float2 bb = *(const float2*)(bias + c);
          float v0 = acc[mi][ni][2 * half + 0] + bb.x;
          float v1 = acc[mi][ni][2 * half + 1] + bb.y;
          v0 = 0.5f * v0 * (1.0f + erff(v0 * 0.7071067811865476f));
          v1 = 0.5f * v1 * (1.0f + erff(v1 * 0.7071067811865476f));
          __half2 hh;
          hh.x = __float2half(v0);
          hh.y = __float2half(v1);
          *(__half2*)(out_h + off) = hh;
        }
      } else {
#pragma unroll
        for (int ni = 0; ni < 4; ni++) {
          int c = col0 + warp_col * 32 + ni * 8 + tig * 2;
          size_t off = (size_t)r * 256 + c;
          float2 bb = *(const float2*)(bias + c);
          float2 ex = *(const float2*)(extra + off);
          float2 v;
          v.x = acc[mi][ni][2 * half + 0] + bb.x + ex.x;
          v.y = acc[mi][ni][2 * half + 1] + bb.y + ex.y;
          *(float2*)(out + off) = v;
        }
      }
    }
  }
}

// ---------------- windowed attention: one block per (window, head) ---------
__global__ void __launch_bounds__(256) attn_kernel(
    const float* __restrict__ rel_table) {
  __shared__ float qs[64 * 32];
  __shared__ float kT[32 * 64];
  __shared__ float vs[64 * 32];
  __shared__ float Ps[64 * 64];
  __shared__ float rel_s[225];
  __shared__ int rid_s[64];

  int tid = threadIdx.x;
  int gw = blockIdx.x;
  int head = blockIdx.y;
  size_t base = ((size_t)gw * 8 + head) * 2048;
  const __half* qg = g_qkv + base;
  const __half* kg = g_qkv + (size_t)TOK * CDIM + base;
  const __half* vg = g_qkv + 2 * (size_t)TOK * CDIM + base;

  {
    int e = tid * 8;
    uint4 qa = *(const uint4*)(qg + e);
    uint4 va = *(const uint4*)(vg + e);
    const __half* qh = (const __half*)&qa;
    const __half* vh = (const __half*)&va;
#pragma unroll
    for (int u = 0; u < 8; u++) {
      qs[e + u] = __half2float(qh[u]);
      vs[e + u] = __half2float(vh[u]);
    }
    uint4 ka = *(const uint4*)(kg + e);
    const __half* kh = (const __half*)&ka;
    int row = e >> 5, c0 = e & 31;
#pragma unroll
    for (int u = 0; u < 8; u++) kT[(c0 + u) * 64 + row] = __half2float(kh[u]);
  }
  if (tid < 225) rel_s[tid] = rel_table[tid * 8 + head];
  if (tid < 64) {
    int nw = gw & 63;
    int h = (nw >> 3) * 8 + (tid >> 3);
    int w = (nw & 7) * 8 + (tid & 7);
    int rh = h < 56 ? 0 : (h < 60 ? 1 : 2);
    int rw = w < 56 ? 0 : (w < 60 ? 1 : 2);
    rid_s[tid] = rh * 3 + rw;
  }
  __syncthreads();

  int r0 = (tid >> 4) * 4;
  int c0 = (tid & 15) * 4;
  float acc[4][4];
#pragma unroll
  for (int u = 0; u < 4; u++)
#pragma unroll
    for (int v = 0; v < 4; v++) acc[u][v] = 0.0f;
#pragma unroll
  for (int kk = 0; kk < 32; kk++) {
    float qr[4];
#pragma unroll
    for (int u = 0; u < 4; u++) qr[u] = qs[(r0 + u) * 32 + kk];
    float4 kv = *(const float4*)&kT[kk * 64 + c0];
    float kr[4] = {kv.x, kv.y, kv.z, kv.w};
#pragma unroll
    for (int u = 0; u < 4; u++)
#pragma unroll
      for (int v = 0; v < 4; v++) acc[u][v] = fmaf(qr[u], kr[v], acc[u][v]);
  }
  const float scale = 0.17677669529663687f;
#pragma unroll
  for (int u = 0; u < 4; u++) {
    int n = r0 + u;
    int in_ = n >> 3, jn = n & 7;
    int ridn = rid_s[n];
    float tmp[4];
#pragma unroll
    for (int v = 0; v < 4; v++) {
      int m = c0 + v;
      int di = in_ - (m >> 3) + 7;
      int dj = jn - (m & 7) + 7;
      float sv = acc[u][v] * scale + rel_s[di * 15 + dj];
      if (ridn != rid_s[m]) sv -= 100.0f;
      tmp[v] = sv;
    }
    *(float4*)&Ps[n * 64 + c0] = make_float4(tmp[0], tmp[1], tmp[2], tmp[3]);
  }
  __syncthreads();

  int warp = tid >> 5, lane = tid & 31;
#pragma unroll
  for (int rr = 0; rr < 8; rr++) {
    int row = warp * 8 + rr;
    float a = Ps[row * 64 + lane];
    float b = Ps[row * 64 + lane + 32];
    float mx = fmaxf(a, b);
#pragma unroll
    for (int o = 16; o; o >>= 1) mx = fmaxf(mx, __shfl_xor_sync(0xffffffffu, mx, o));
    float e1 = __expf(a - mx), e2 = __expf(b - mx);
    float sm = e1 + e2;
#pragma unroll
    for (int o = 16; o; o >>= 1) sm += __shfl_xor_sync(0xffffffffu, sm, o);
    float inv = 1.0f / sm;
    Ps[row * 64 + lane] = e1 * inv;
    Ps[row * 64 + lane + 32] = e2 * inv;
  }
  __syncthreads();

  int row = tid >> 2;
  int db = (tid & 3) * 8;
  float o[8];
#pragma unroll
  for (int u = 0; u < 8; u++) o[u] = 0.0f;
#pragma unroll
  for (int m = 0; m < 64; m++) {
    float p = Ps[row * 64 + m];
    float4 va = *(const float4*)&vs[m * 32 + db];
    float4 vb = *(const float4*)&vs[m * 32 + db + 4];
    o[0] = fmaf(p, va.x, o[0]);
    o[1] = fmaf(p, va.y, o[1]);
    o[2] = fmaf(p, va.z, o[2]);
    o[3] = fmaf(p, va.w, o[3]);
    o[4] = fmaf(p, vb.x, o[4]);
    o[5] = fmaf(p, vb.y, o[5]);
    o[6] = fmaf(p, vb.z, o[6]);
    o[7] = fmaf(p, vb.w, o[7]);
  }
  __half h8[8];
#pragma unroll
  for (int u = 0; u < 8; u++) h8[u] = __float2half(o[u]);
  *(uint4*)(g_ctx_h + ((size_t)gw * 64 + row) * 256 + head * 32 + db) = *(uint4*)h8;
}

// ---------------- host ----------------
extern "C" void kernel_launch(void* const* d_in, const int* in_sizes, int n_in,
                              void* d_out, int out_size) {
  (void)in_sizes; (void)n_in; (void)out_size;
  const float* hs   = (const float*)d_in[0];
  const float* ln1g = (const float*)d_in[1];
  const float* ln1b = (const float*)d_in[2];
  const float* wq   = (const float*)d_in[3];
  const float* bq   = (const float*)d_in[4];
  const float* wk   = (const float*)d_in[5];
  const float* bk   = (const float*)d_in[6];
  const float* wv   = (const float*)d_in[7];
  const float* bv   = (const float*)d_in[8];
  const float* rel  = (const float*)d_in[9];
  const float* wo   = (const float*)d_in[10];
  const float* bo   = (const float*)d_in[11];
  const float* ln2g = (const float*)d_in[12];
  const float* ln2b = (const float*)d_in[13];
  const float* w1   = (const float*)d_in[14];
  const float* b1   = (const float*)d_in[15];
  const float* w2   = (const float*)d_in[16];
  const float* b2   = (const float*)d_in[17];
  float* out = (float*)d_out;

  __half *xh, *yh, *cxh, *ith, *wqkvh, *woh, *w1h, *w2h;
  float *bqkv, *hid;
  cudaGetSymbolAddress((void**)&xh, g_x_h);
  cudaGetSymbolAddress((void**)&yh, g_y_h);
  cudaGetSymbolAddress((void**)&cxh, g_ctx_h);
  cudaGetSymbolAddress((void**)&ith, g_int_h);
  cudaGetSymbolAddress((void**)&wqkvh, g_wqkv_h);
  cudaGetSymbolAddress((void**)&woh, g_wo_h);
  cudaGetSymbolAddress((void**)&w1h, g_w1_h);
  cudaGetSymbolAddress((void**)&w2h, g_w2_h);
  cudaGetSymbolAddress((void**)&bqkv, g_bqkv);
  cudaGetSymbolAddress((void**)&hid, g_hidden);

  const int SMSZ = 4 * 20480;  // 4 stages
  cudaFuncSetAttribute(gemm_mma<0>, cudaFuncAttributeMaxDynamicSharedMemorySize, SMSZ);
  cudaFuncSetAttribute(gemm_mma<1>, cudaFuncAttributeMaxDynamicSharedMemorySize, SMSZ);
  cudaFuncSetAttribute(gemm_mma<2>, cudaFuncAttributeMaxDynamicSharedMemorySize, SMSZ);
  cudaFuncSetAttribute(gemm_mma<3>, cudaFuncAttributeMaxDynamicSharedMemorySize, SMSZ);

  prep_weights<<<768, 256>>>(wq, wk, wv, wo, w1, w2, bq, bk, bv);

  ln_h<true><<<4096, 256>>>(hs, ln1g, ln1b, xh);

  gemm_mma<0><<<dim3(6, 256), 256, SMSZ>>>(xh, wqkvh, bqkv, nullptr, nullptr,
                                           nullptr, 256);

  attn_kernel<<<dim3(512, 8), 256>>>(rel);

  gemm_mma<1><<<dim3(2, 256), 256, SMSZ>>>(cxh, woh, bo, hid, nullptr, hs, 256);

  ln_h<false><<<4096, 256>>>(hid, ln2g, ln2b, yh);

  gemm_mma<2><<<dim3(8, 256), 256, SMSZ>>>(yh, w1h, b1, nullptr, ith, nullptr, 256);

  gemm_mma<3><<<dim3(2, 256), 256, SMSZ>>>(ith, w2h, b2, out, nullptr, hid, 1024);
}

// round 7
// speedup vs baseline: 5.4323x; 1.3555x over previous
#include <cuda_runtime.h>
#include <cuda_fp16.h>
#include <math.h>
#include <stdint.h>

#define TOK 32768
#define CDIM 256
#define MLPD 1024

// ---------------- device scratch ----------------
__device__ __half g_x_h[TOK * CDIM];        // LN1 output (windowed order)
__device__ __half g_y_h[TOK * CDIM];        // LN2 output
__device__ __half g_ctx_h[TOK * CDIM];      // attention context (windowed order)
__device__ __half g_int_h[TOK * MLPD];      // MLP hidden
__device__ __half g_wqkv_h[3 * CDIM * CDIM];
__device__ __half g_wo_h[CDIM * CDIM];
__device__ __half g_w1_h[MLPD * CDIM];
__device__ __half g_w2_h[CDIM * MLPD];
__device__ float g_bqkv[3 * CDIM];
__device__ __half g_qkv[3 * TOK * CDIM];    // [sel][win][head][n][d]
__device__ float g_hidden[TOK * CDIM];

// ---------------- helpers ----------------
__device__ __forceinline__ uint32_t smem_u32(const void* p) {
  uint32_t a;
  asm("{ .reg .u64 t; cvta.to.shared.u64 t, %1; cvt.u32.u64 %0, t; }"
      : "=r"(a) : "l"(p));
  return a;
}

__device__ __forceinline__ void cp16(uint32_t smem, const void* g) {
  asm volatile("cp.async.cg.shared.global [%0], [%1], 16;" :: "r"(smem), "l"(g));
}
#define CP_COMMIT() asm volatile("cp.async.commit_group;" ::: "memory")
#define CP_WAIT2() asm volatile("cp.async.wait_group 2;" ::: "memory")

#define LDSM4(r, addr) \
  asm volatile("ldmatrix.sync.aligned.m8n8.x4.shared.b16 {%0,%1,%2,%3}, [%4];" \
               : "=r"((r)[0]), "=r"((r)[1]), "=r"((r)[2]), "=r"((r)[3]) \
               : "r"(addr))

#define LDSM4T(r, addr) \
  asm volatile("ldmatrix.sync.aligned.m8n8.x4.trans.shared.b16 {%0,%1,%2,%3}, [%4];" \
               : "=r"((r)[0]), "=r"((r)[1]), "=r"((r)[2]), "=r"((r)[3]) \
               : "r"(addr))

#define MMA16816(d, a, b0, b1) \
  asm volatile( \
      "mma.sync.aligned.m16n8k16.row.col.f32.f16.f16.f32 " \
      "{%0,%1,%2,%3}, {%4,%5,%6,%7}, {%8,%9}, {%0,%1,%2,%3};" \
      : "+f"((d)[0]), "+f"((d)[1]), "+f"((d)[2]), "+f"((d)[3]) \
      : "r"((a)[0]), "r"((a)[1]), "r"((a)[2]), "r"((a)[3]), \
        "r"(b0), "r"(b1))

// windowed token index -> original token index (+4 cyclic shift)
__device__ __forceinline__ int map_shift(int t) {
  int b = t >> 12, rr = t & 4095;
  int win = rr >> 6, n = rr & 63;
  int wh = win >> 3, ww = win & 7, i = n >> 3, j = n & 7;
  int h = (wh * 8 + i + 4) & 63;
  int w = (ww * 8 + j + 4) & 63;
  return (b << 12) + (h << 6) + w;
}

// ---------------- LayerNorm -> fp16 (one warp per token) -------------------
template <bool GATHER>
__global__ void __launch_bounds__(256) ln_h(
    const float* __restrict__ x, const float* __restrict__ gam,
    const float* __restrict__ bet, __half* __restrict__ oh) {
  int warp = threadIdx.x >> 5, lane = threadIdx.x & 31;
  int t = blockIdx.x * 8 + warp;
  int src = GATHER ? map_shift(t) : t;
  const float4* xr = (const float4*)(x + (size_t)src * CDIM);
  float4 v0 = xr[lane], v1 = xr[lane + 32];
  float s = v0.x + v0.y + v0.z + v0.w + v1.x + v1.y + v1.z + v1.w;
  float q = v0.x * v0.x + v0.y * v0.y + v0.z * v0.z + v0.w * v0.w +
            v1.x * v1.x + v1.y * v1.y + v1.z * v1.z + v1.w * v1.w;
#pragma unroll
  for (int o = 16; o; o >>= 1) {
    s += __shfl_xor_sync(0xffffffffu, s, o);
    q += __shfl_xor_sync(0xffffffffu, q, o);
  }
  float mean = s * (1.0f / 256.0f);
  float var = q * (1.0f / 256.0f) - mean * mean;
  float rs = rsqrtf(var + 1e-5f);
  const float4* g4 = (const float4*)gam;
  const float4* b4 = (const float4*)bet;
  __half h[4];
  {
    float4 ga = g4[lane], be = b4[lane];
    h[0] = __float2half((v0.x - mean) * rs * ga.x + be.x);
    h[1] = __float2half((v0.y - mean) * rs * ga.y + be.y);
    h[2] = __float2half((v0.z - mean) * rs * ga.z + be.z);
    h[3] = __float2half((v0.w - mean) * rs * ga.w + be.w);
    *(uint2*)(oh + (size_t)t * CDIM + lane * 4) = *(uint2*)h;
  }
  {
    float4 ga = g4[lane + 32], be = b4[lane + 32];
    h[0] = __float2half((v1.x - mean) * rs * ga.x + be.x);
    h[1] = __float2half((v1.y - mean) * rs * ga.y + be.y);
    h[2] = __float2half((v1.z - mean) * rs * ga.z + be.z);
    h[3] = __float2half((v1.w - mean) * rs * ga.w + be.w);
    *(uint2*)(oh + (size_t)t * CDIM + 128 + lane * 4) = *(uint2*)h;
  }
}

// ---------------- merged weight prep: one launch -------------------------
__global__ void __launch_bounds__(256) prep_weights(
    const float* __restrict__ wq, const float* __restrict__ wk,
    const float* __restrict__ wv, const float* __restrict__ wo,
    const float* __restrict__ w1, const float* __restrict__ w2,
    const float* __restrict__ bq, const float* __restrict__ bk,
    const float* __restrict__ bv) {
  int j = blockIdx.x * 256 + threadIdx.x;  // float4 index, total 196608
  const float* src;
  __half* dst;
  int loc;
  if (j < 16384) { src = wq; dst = g_wqkv_h; loc = j; }
  else if (j < 32768) { src = wk; dst = g_wqkv_h + 65536; loc = j - 16384; }
  else if (j < 49152) { src = wv; dst = g_wqkv_h + 131072; loc = j - 32768; }
  else if (j < 65536) { src = wo; dst = g_wo_h; loc = j - 49152; }
  else if (j < 131072) { src = w1; dst = g_w1_h; loc = j - 65536; }
  else { src = w2; dst = g_w2_h; loc = j - 131072; }
  float4 v = ((const float4*)src)[loc];
  __half h[4];
  h[0] = __float2half(v.x);
  h[1] = __float2half(v.y);
  h[2] = __float2half(v.z);
  h[3] = __float2half(v.w);
  *(uint2*)(dst + loc * 4) = *(uint2*)h;
  int g = j;
  if (g < 256) g_bqkv[g] = bq[g];
  else if (g < 512) g_bqkv[g] = bk[g - 256];
  else if (g < 768) g_bqkv[g] = bv[g - 512];
}

// ---------------- HMMA fp16 GEMM, cp.async 4-stage pipeline ----------------
template <int EPI>
__global__ void __launch_bounds__(256, 2) gemm_mma(
    const __half* __restrict__ A, const __half* __restrict__ B,
    const float* __restrict__ bias, float* __restrict__ out,
    __half* __restrict__ out_h, const float* __restrict__ extra, int K) {
  extern __shared__ char smraw[];
  const int STG = 20480;
  int tid = threadIdx.x, wid = tid >> 5, lane = tid & 31;
  int warp_row = wid >> 2, warp_col = wid & 3;
  int row0 = blockIdx.y * 128, col0 = blockIdx.x * 128;
  uint32_t sm = smem_u32(smraw);

  float acc[4][4][4];
#pragma unroll
  for (int mi = 0; mi < 4; mi++)
#pragma unroll
    for (int ni = 0; ni < 4; ni++)
#pragma unroll
      for (int u = 0; u < 4; u++) acc[mi][ni][u] = 0.0f;

  int lrow = tid >> 2;
  int lchunk = tid & 3;
  int nslabs = K >> 5;

  const __half* Ab = A + (size_t)row0 * K + lchunk * 8;
  const __half* Bb = B + (size_t)col0 * K + lchunk * 8;
  uint32_t soff = lrow * 80 + lchunk * 16;

#pragma unroll
  for (int p = 0; p < 3; p++) {
    uint32_t st = sm + p * STG;
    int k0 = p * 32;
#pragma unroll
    for (int r = 0; r < 2; r++) {
      int row = lrow + r * 64;
      cp16(st + soff + r * 64 * 80, Ab + (size_t)row * K + k0);
      cp16(st + 10240 + soff + r * 64 * 80, Bb + (size_t)row * K + k0);
    }
    CP_COMMIT();
  }

  int a_r = warp_row * 64 + (lane & 15);
  int b_r = warp_col * 32 + (lane & 15);
  int oct = lane >> 4;

  for (int s = 0; s < nslabs; s++) {
    CP_WAIT2();
    __syncthreads();
    if (s + 3 < nslabs) {
      uint32_t st = sm + ((s + 3) & 3) * STG;
      int k0 = (s + 3) * 32;
#pragma unroll
      for (int r = 0; r < 2; r++) {
        int row = lrow + r * 64;
        cp16(st + soff + r * 64 * 80, Ab + (size_t)row * K + k0);
        cp16(st + 10240 + soff + r * 64 * 80, Bb + (size_t)row * K + k0);
      }
    }
    CP_COMMIT();

    uint32_t st = sm + (s & 3) * STG;
#pragma unroll
    for (int kk = 0; kk < 2; kk++) {
      uint32_t ah[4][4];
#pragma unroll
      for (int mi = 0; mi < 4; mi++) {
        uint32_t addr = st + (a_r + mi * 16) * 80 + (2 * kk + oct) * 16;
        LDSM4(ah[mi], addr);
      }
      uint32_t bh[2][4];
#pragma unroll
      for (int nb = 0; nb < 2; nb++) {
        uint32_t addr = st + 10240 + (b_r + nb * 16) * 80 + (2 * kk + oct) * 16;
        LDSM4(bh[nb], addr);
      }
#pragma unroll
      for (int mi = 0; mi < 4; mi++)
#pragma unroll
        for (int ni = 0; ni < 4; ni++) {
          int nb = ni >> 1, up = ni & 1;
          MMA16816(acc[mi][ni], ah[mi], bh[nb][up], bh[nb][up + 2]);
        }
    }
  }

  int group = lane >> 2, tig = lane & 3;
#pragma unroll
  for (int mi = 0; mi < 4; mi++) {
#pragma unroll
    for (int half = 0; half < 2; half++) {
      int r = row0 + warp_row * 64 + mi * 16 + group + 8 * half;
      if (EPI == 0) {
        int win = r >> 6, n = r & 63;
#pragma unroll
        for (int ni = 0; ni < 4; ni++) {
          int c = col0 + warp_col * 32 + ni * 8 + tig * 2;
          int sel = c >> 8, cw = c & 255;
          int head = cw >> 5, d = cw & 31;
          float2 bb = *(const float2*)(bias + c);
          __half2 v;
          v.x = __float2half(acc[mi][ni][2 * half + 0] + bb.x);
          v.y = __float2half(acc[mi][ni][2 * half + 1] + bb.y);
          *(__half2*)(g_qkv + (size_t)sel * (TOK * CDIM) + (size_t)win * 16384 +
                      head * 2048 + n * 32 + d) = v;
        }
      } else if (EPI == 1) {
        int dst = map_shift(r);
#pragma unroll
        for (int ni = 0; ni < 4; ni++) {
          int c = col0 + warp_col * 32 + ni * 8 + tig * 2;
          size_t off = (size_t)dst * 256 + c;
          float2 bb = *(const float2*)(bias + c);
          float2 ex = *(const float2*)(extra + off);
          float2 v;
          v.x = acc[mi][ni][2 * half + 0] + bb.x + ex.x;
          v.y = acc[mi][ni][2 * half + 1] + bb.y + ex.y;
          *(float2*)(out + off) = v;
        }
      } else if (EPI == 2) {
#pragma unroll
        for (int ni = 0; ni < 4; ni++) {
          int c = col0 + warp_col * 32 + ni * 8 + tig * 2;
          size_t off = (size_t)r * MLPD + c;
          float2 bb = *(const float2*)(bias + c);
          float v0 = acc[mi][ni][2 * half + 0] + bb.x;
          float v1 = acc[mi][ni][2 * half + 1] + bb.y;
          v0 = 0.5f * v0 * (1.0f + erff(v0 * 0.7071067811865476f));
          v1 = 0.5f * v1 * (1.0f + erff(v1 * 0.7071067811865476f));
          __half2 hh;
          hh.x = __float2half(v0);
          hh.y = __float2half(v1);
          *(__half2*)(out_h + off) = hh;
        }
      } else {
#pragma unroll
        for (int ni = 0; ni < 4; ni++) {
          int c = col0 + warp_col * 32 + ni * 8 + tig * 2;
          size_t off = (size_t)r * 256 + c;
          float2 bb = *(const float2*)(bias + c);
          float2 ex = *(const float2*)(extra + off);
          float2 v;
          v.x = acc[mi][ni][2 * half + 0] + bb.x + ex.x;
          v.y = acc[mi][ni][2 * half + 1] + bb.y + ex.y;
          *(float2*)(out + off) = v;
        }
      }
    }
  }
}

// ---------------- tensor-core windowed attention --------------------------
// block = 256 thr = 8 warps, handles (window, 4-head group).
// warp = (head_local = wid>>1, row-half = wid&1): 32 q-rows x 64 tokens.
// smem: q/k/v [4 heads][64 rows][80B stride fp16], rel[4][225] f32.
__global__ void __launch_bounds__(256) attn_mma(
    const float* __restrict__ rel_table) {
  extern __shared__ char smraw[];
  const int QOFF = 0, KOFF = 20480, VOFF = 40960, ROFF = 61440;
  int tid = threadIdx.x, wid = tid >> 5, lane = tid & 31;
  int win = blockIdx.x >> 1;
  int hgrp = (blockIdx.x & 1) * 4;
  uint32_t smb = smem_u32(smraw);

  size_t gbase = (size_t)win * 16384 + (size_t)hgrp * 2048;
  const __half* qg = g_qkv + gbase;
  const __half* kg = g_qkv + (size_t)TOK * CDIM + gbase;
  const __half* vg = g_qkv + 2 * (size_t)TOK * CDIM + gbase;

#pragma unroll
  for (int p = 0; p < 4; p++) {
    int e = p * 2048 + tid * 8;
    int hl = e >> 11, r = (e >> 5) & 63, ck = (e >> 3) & 3;
    uint32_t so = hl * 5120 + r * 80 + ck * 16;
    *(uint4*)(smraw + QOFF + so) = *(const uint4*)(qg + e);
    *(uint4*)(smraw + KOFF + so) = *(const uint4*)(kg + e);
    *(uint4*)(smraw + VOFF + so) = *(const uint4*)(vg + e);
  }
  for (int i = tid; i < 900; i += 256) {
    int hl = i / 225, idx = i - hl * 225;
    *(float*)(smraw + ROFF + hl * 900 + idx * 4) = rel_table[idx * 8 + hgrp + hl];
  }
  __syncthreads();

  int head_l = wid >> 1;
  int rb = (wid & 1) * 32;
  uint32_t qb = smb + QOFF + head_l * 5120;
  uint32_t kb = smb + KOFF + head_l * 5120;
  uint32_t vb = smb + VOFF + head_l * 5120;
  const float* relh = (const float*)(smraw + ROFF + head_l * 900);

  int g = lane >> 2, t = lane & 3;
  int oct = lane >> 4;

  // --- Q fragments (A operand) ---
  uint32_t qa[2][2][4];
#pragma unroll
  for (int mi = 0; mi < 2; mi++)
#pragma unroll
    for (int kt = 0; kt < 2; kt++) {
      uint32_t addr = qb + (rb + mi * 16 + (lane & 15)) * 80 +
                      (oct * 8 + kt * 16) * 2;
      LDSM4(qa[mi][kt], addr);
    }

  // --- K fragments (B operand: k=d, n=token; K[token][d] is already
  //     col-major B -> PLAIN ldmatrix, GEMM-B-style addressing) ---
  // kf[kt][nt] = {b0 (d kt*16..+7), b1 (d kt*16+8..+15)} for tokens nt*8..+7
  uint32_t kf[2][8][2];
#pragma unroll
  for (int j = 0; j < 4; j++)
#pragma unroll
    for (int kt = 0; kt < 2; kt++) {
      uint32_t r4[4];
      uint32_t addr = kb + (j * 16 + (lane & 15)) * 80 + (kt * 16 + oct * 8) * 2;
      LDSM4(r4, addr);
      kf[kt][j * 2 + 0][0] = r4[0];  // tokens j*16+0..7,  d lo
      kf[kt][j * 2 + 0][1] = r4[2];  // tokens j*16+0..7,  d hi
      kf[kt][j * 2 + 1][0] = r4[1];  // tokens j*16+8..15, d lo
      kf[kt][j * 2 + 1][1] = r4[3];  // tokens j*16+8..15, d hi
    }

  // --- S = Q @ K^T ---
  float sc[2][8][4];
#pragma unroll
  for (int mi = 0; mi < 2; mi++)
#pragma unroll
    for (int nt = 0; nt < 8; nt++) {
#pragma unroll
      for (int u = 0; u < 4; u++) sc[mi][nt][u] = 0.0f;
      MMA16816(sc[mi][nt], qa[mi][0], kf[0][nt][0], kf[0][nt][1]);
      MMA16816(sc[mi][nt], qa[mi][1], kf[1][nt][0], kf[1][nt][1]);
    }

  // --- scale + rel bias + mask, in-register softmax ---
  int nw = win & 63;
  bool eh = (nw >> 3) == 7, ew = (nw & 7) == 7;
  const float scale = 0.17677669529663687f;
  float inv[2][2];
#pragma unroll
  for (int mi = 0; mi < 2; mi++) {
    float rmax[2] = {-1e30f, -1e30f};
#pragma unroll
    for (int h2 = 0; h2 < 2; h2++) {
      int n = rb + mi * 16 + g + 8 * h2;
      int ni_ = n >> 3, nj = n & 7;
      int ridn = (eh ? (ni_ < 4 ? 1 : 2) : 0) * 3 + (ew ? (nj < 4 ? 1 : 2) : 0);
#pragma unroll
      for (int nt = 0; nt < 8; nt++) {
#pragma unroll
        for (int j = 0; j < 2; j++) {
          int m = nt * 8 + 2 * t + j;
          int mi_ = m >> 3, mj = m & 7;
          int ridm = (eh ? (mi_ < 4 ? 1 : 2) : 0) * 3 + (ew ? (mj < 4 ? 1 : 2) : 0);
          float s = sc[mi][nt][2 * h2 + j] * scale +
                    relh[(ni_ - mi_ + 7) * 15 + (nj - mj + 7)];
          if (ridn != ridm) s -= 100.0f;
          sc[mi][nt][2 * h2 + j] = s;
          rmax[h2] = fmaxf(rmax[h2], s);
        }
      }
    }
#pragma unroll
    for (int h2 = 0; h2 < 2; h2++) {
      rmax[h2] = fmaxf(rmax[h2], __shfl_xor_sync(0xffffffffu, rmax[h2], 1));
      rmax[h2] = fmaxf(rmax[h2], __shfl_xor_sync(0xffffffffu, rmax[h2], 2));
    }
    float rsum[2] = {0.0f, 0.0f};
#pragma unroll
    for (int nt = 0; nt < 8; nt++)
#pragma unroll
      for (int u = 0; u < 4; u++) {
        int h2 = u >> 1;
        float e = __expf(sc[mi][nt][u] - rmax[h2]);
        sc[mi][nt][u] = e;
        rsum[h2] += e;
      }
#pragma unroll
    for (int h2 = 0; h2 < 2; h2++) {
      rsum[h2] += __shfl_xor_sync(0xffffffffu, rsum[h2], 1);
      rsum[h2] += __shfl_xor_sync(0xffffffffu, rsum[h2], 2);
      inv[mi][h2] = 1.0f / rsum[h2];
    }
  }

  // --- P fragments (accumulator -> A operand relayout, fp16) ---
  uint32_t ph[2][4][4];
#pragma unroll
  for (int mi = 0; mi < 2; mi++)
#pragma unroll
    for (int kt = 0; kt < 4; kt++) {
      __half2 a0 = __floats2half2_rn(sc[mi][2 * kt][0], sc[mi][2 * kt][1]);
      __half2 a1 = __floats2half2_rn(sc[mi][2 * kt][2], sc[mi][2 * kt][3]);
      __half2 a2 = __floats2half2_rn(sc[mi][2 * kt + 1][0], sc[mi][2 * kt + 1][1]);
      __half2 a3 = __floats2half2_rn(sc[mi][2 * kt + 1][2], sc[mi][2 * kt + 1][3]);
      ph[mi][kt][0] = *(uint32_t*)&a0;
      ph[mi][kt][1] = *(uint32_t*)&a1;
      ph[mi][kt][2] = *(uint32_t*)&a2;
      ph[mi][kt][3] = *(uint32_t*)&a3;
    }

  // --- V fragments (B operand: k=token, n=d; needs TRANS ldmatrix) ---
  // vf[kt][ni] = {b0 (tokens kt*16..+7), b1 (tokens kt*16+8..+15)} for d ni*8..+7
  uint32_t vf[4][4][2];
#pragma unroll
  for (int kt = 0; kt < 4; kt++)
#pragma unroll
    for (int np = 0; np < 2; np++) {
      uint32_t r4[4];
      uint32_t addr = vb + (kt * 16 + (lane & 15)) * 80 + (np * 16 + oct * 8) * 2;
      LDSM4T(r4, addr);
      vf[kt][np * 2 + 0][0] = r4[0];  // tokens lo, d np*16+0..7
      vf[kt][np * 2 + 0][1] = r4[1];  // tokens hi, d np*16+0..7
      vf[kt][np * 2 + 1][0] = r4[2];  // tokens lo, d np*16+8..15
      vf[kt][np * 2 + 1][1] = r4[3];  // tokens hi, d np*16+8..15
    }

  // --- O = P @ V ---
  float oc[2][4][4];
#pragma unroll
  for (int mi = 0; mi < 2; mi++)
#pragma unroll
    for (int ni = 0; ni < 4; ni++) {
#pragma unroll
      for (int u = 0; u < 4; u++) oc[mi][ni][u] = 0.0f;
#pragma unroll
      for (int kt = 0; kt < 4; kt++)
        MMA16816(oc[mi][ni], ph[mi][kt], vf[kt][ni][0], vf[kt][ni][1]);
    }

  // --- store (deferred softmax normalization) ---
  int head = hgrp + head_l;
#pragma unroll
  for (int mi = 0; mi < 2; mi++)
#pragma unroll
    for (int h2 = 0; h2 < 2; h2++) {
      int n = rb + mi * 16 + g + 8 * h2;
      float iv = inv[mi][h2];
#pragma unroll
      for (int ni = 0; ni < 4; ni++) {
        int d = ni * 8 + 2 * t;
        __half2 hv = __floats2half2_rn(oc[mi][ni][2 * h2 + 0] * iv,
                                       oc[mi][ni][2 * h2 + 1] * iv);
        *(__half2*)(g_ctx_h + ((size_t)win * 64 + n) * 256 + head * 32 + d) = hv;
      }
    }
}

// ---------------- host ----------------
extern "C" void kernel_launch(void* const* d_in, const int* in_sizes, int n_in,
                              void* d_out, int out_size) {
  (void)in_sizes; (void)n_in; (void)out_size;
  const float* hs   = (const float*)d_in[0];
  const float* ln1g = (const float*)d_in[1];
  const float* ln1b = (const float*)d_in[2];
  const float* wq   = (const float*)d_in[3];
  const float* bq   = (const float*)d_in[4];
  const float* wk   = (const float*)d_in[5];
  const float* bk   = (const float*)d_in[6];
  const float* wv   = (const float*)d_in[7];
  const float* bv   = (const float*)d_in[8];
  const float* rel  = (const float*)d_in[9];
  const float* wo   = (const float*)d_in[10];
  const float* bo   = (const float*)d_in[11];
  const float* ln2g = (const float*)d_in[12];
  const float* ln2b = (const float*)d_in[13];
  const float* w1   = (const float*)d_in[14];
  const float* b1   = (const float*)d_in[15];
  const float* w2   = (const float*)d_in[16];
  const float* b2   = (const float*)d_in[17];
  float* out = (float*)d_out;

  __half *xh, *yh, *cxh, *ith, *wqkvh, *woh, *w1h, *w2h;
  float *bqkv, *hid;
  cudaGetSymbolAddress((void**)&xh, g_x_h);
  cudaGetSymbolAddress((void**)&yh, g_y_h);
  cudaGetSymbolAddress((void**)&cxh, g_ctx_h);
  cudaGetSymbolAddress((void**)&ith, g_int_h);
  cudaGetSymbolAddress((void**)&wqkvh, g_wqkv_h);
  cudaGetSymbolAddress((void**)&woh, g_wo_h);
  cudaGetSymbolAddress((void**)&w1h, g_w1_h);
  cudaGetSymbolAddress((void**)&w2h, g_w2_h);
  cudaGetSymbolAddress((void**)&bqkv, g_bqkv);
  cudaGetSymbolAddress((void**)&hid, g_hidden);

  const int SMSZ = 4 * 20480;
  cudaFuncSetAttribute(gemm_mma<0>, cudaFuncAttributeMaxDynamicSharedMemorySize, SMSZ);
  cudaFuncSetAttribute(gemm_mma<1>, cudaFuncAttributeMaxDynamicSharedMemorySize, SMSZ);
  cudaFuncSetAttribute(gemm_mma<2>, cudaFuncAttributeMaxDynamicSharedMemorySize, SMSZ);
  cudaFuncSetAttribute(gemm_mma<3>, cudaFuncAttributeMaxDynamicSharedMemorySize, SMSZ);
  const int ASM = 61440 + 3600;
  cudaFuncSetAttribute(attn_mma, cudaFuncAttributeMaxDynamicSharedMemorySize, ASM);

  prep_weights<<<768, 256>>>(wq, wk, wv, wo, w1, w2, bq, bk, bv);

  ln_h<true><<<4096, 256>>>(hs, ln1g, ln1b, xh);

  gemm_mma<0><<<dim3(6, 256), 256, SMSZ>>>(xh, wqkvh, bqkv, nullptr, nullptr,
                                           nullptr, 256);

  attn_mma<<<1024, 256, ASM>>>(rel);

  gemm_mma<1><<<dim3(2, 256), 256, SMSZ>>>(cxh, woh, bo, hid, nullptr, hs, 256);

  ln_h<false><<<4096, 256>>>(hid, ln2g, ln2b, yh);

  gemm_mma<2><<<dim3(8, 256), 256, SMSZ>>>(yh, w1h, b1, nullptr, ith, nullptr, 256);

  gemm_mma<3><<<dim3(2, 256), 256, SMSZ>>>(ith, w2h, b2, out, nullptr, hid, 1024);
}

// round 8
// speedup vs baseline: 5.6393x; 1.0381x over previous
#include <cuda_runtime.h>
#include <cuda_fp16.h>
#include <math.h>
#include <stdint.h>

#define TOK 32768
#define CDIM 256
#define MLPD 1024

// ---------------- device scratch ----------------
__device__ __half g_x_h[TOK * CDIM];        // LN1 output (windowed order)
__device__ __half g_y_h[TOK * CDIM];        // LN2 output
__device__ __half g_ctx_h[TOK * CDIM];      // attention context (windowed order)
__device__ __half g_int_h[TOK * MLPD];      // MLP hidden
__device__ __half g_wqkv_h[3 * CDIM * CDIM];
__device__ __half g_wo_h[CDIM * CDIM];
__device__ __half g_w1_h[MLPD * CDIM];
__device__ __half g_w2_h[CDIM * MLPD];
__device__ float g_bqkv[3 * CDIM];
__device__ __half g_qkv[3 * TOK * CDIM];    // [sel][win][head][n][d]
__device__ float g_hidden[TOK * CDIM];

// ---------------- helpers ----------------
__device__ __forceinline__ uint32_t smem_u32(const void* p) {
  uint32_t a;
  asm("{ .reg .u64 t; cvta.to.shared.u64 t, %1; cvt.u32.u64 %0, t; }"
      : "=r"(a) : "l"(p));
  return a;
}

__device__ __forceinline__ void cp16(uint32_t smem, const void* g) {
  asm volatile("cp.async.cg.shared.global [%0], [%1], 16;" :: "r"(smem), "l"(g));
}
#define CP_COMMIT() asm volatile("cp.async.commit_group;" ::: "memory")
#define CP_WAIT2() asm volatile("cp.async.wait_group 2;" ::: "memory")
#define CP_WAIT0() asm volatile("cp.async.wait_group 0;" ::: "memory")

#define LDSM4(r, addr) \
  asm volatile("ldmatrix.sync.aligned.m8n8.x4.shared.b16 {%0,%1,%2,%3}, [%4];" \
               : "=r"((r)[0]), "=r"((r)[1]), "=r"((r)[2]), "=r"((r)[3]) \
               : "r"(addr))

#define LDSM4T(r, addr) \
  asm volatile("ldmatrix.sync.aligned.m8n8.x4.trans.shared.b16 {%0,%1,%2,%3}, [%4];" \
               : "=r"((r)[0]), "=r"((r)[1]), "=r"((r)[2]), "=r"((r)[3]) \
               : "r"(addr))

#define MMA16816(d, a, b0, b1) \
  asm volatile( \
      "mma.sync.aligned.m16n8k16.row.col.f32.f16.f16.f32 " \
      "{%0,%1,%2,%3}, {%4,%5,%6,%7}, {%8,%9}, {%0,%1,%2,%3};" \
      : "+f"((d)[0]), "+f"((d)[1]), "+f"((d)[2]), "+f"((d)[3]) \
      : "r"((a)[0]), "r"((a)[1]), "r"((a)[2]), "r"((a)[3]), \
        "r"(b0), "r"(b1))

// windowed token index -> original token index (+4 cyclic shift)
__device__ __forceinline__ int map_shift(int t) {
  int b = t >> 12, rr = t & 4095;
  int win = rr >> 6, n = rr & 63;
  int wh = win >> 3, ww = win & 7, i = n >> 3, j = n & 7;
  int h = (wh * 8 + i + 4) & 63;
  int w = (ww * 8 + j + 4) & 63;
  return (b << 12) + (h << 6) + w;
}

// ---------------- LayerNorm -> fp16 (one warp per token) -------------------
template <bool GATHER>
__global__ void __launch_bounds__(256) ln_h(
    const float* __restrict__ x, const float* __restrict__ gam,
    const float* __restrict__ bet, __half* __restrict__ oh) {
  int warp = threadIdx.x >> 5, lane = threadIdx.x & 31;
  int t = blockIdx.x * 8 + warp;
  int src = GATHER ? map_shift(t) : t;
  const float4* xr = (const float4*)(x + (size_t)src * CDIM);
  float4 v0 = xr[lane], v1 = xr[lane + 32];
  float s = v0.x + v0.y + v0.z + v0.w + v1.x + v1.y + v1.z + v1.w;
  float q = v0.x * v0.x + v0.y * v0.y + v0.z * v0.z + v0.w * v0.w +
            v1.x * v1.x + v1.y * v1.y + v1.z * v1.z + v1.w * v1.w;
#pragma unroll
  for (int o = 16; o; o >>= 1) {
    s += __shfl_xor_sync(0xffffffffu, s, o);
    q += __shfl_xor_sync(0xffffffffu, q, o);
  }
  float mean = s * (1.0f / 256.0f);
  float var = q * (1.0f / 256.0f) - mean * mean;
  float rs = rsqrtf(var + 1e-5f);
  const float4* g4 = (const float4*)gam;
  const float4* b4 = (const float4*)bet;
  __half h[4];
  {
    float4 ga = g4[lane], be = b4[lane];
    h[0] = __float2half((v0.x - mean) * rs * ga.x + be.x);
    h[1] = __float2half((v0.y - mean) * rs * ga.y + be.y);
    h[2] = __float2half((v0.z - mean) * rs * ga.z + be.z);
    h[3] = __float2half((v0.w - mean) * rs * ga.w + be.w);
    *(uint2*)(oh + (size_t)t * CDIM + lane * 4) = *(uint2*)h;
  }
  {
    float4 ga = g4[lane + 32], be = b4[lane + 32];
    h[0] = __float2half((v1.x - mean) * rs * ga.x + be.x);
    h[1] = __float2half((v1.y - mean) * rs * ga.y + be.y);
    h[2] = __float2half((v1.z - mean) * rs * ga.z + be.z);
    h[3] = __float2half((v1.w - mean) * rs * ga.w + be.w);
    *(uint2*)(oh + (size_t)t * CDIM + 128 + lane * 4) = *(uint2*)h;
  }
}

// ---------------- merged weight prep: one launch -------------------------
__global__ void __launch_bounds__(256) prep_weights(
    const float* __restrict__ wq, const float* __restrict__ wk,
    const float* __restrict__ wv, const float* __restrict__ wo,
    const float* __restrict__ w1, const float* __restrict__ w2,
    const float* __restrict__ bq, const float* __restrict__ bk,
    const float* __restrict__ bv) {
  int j = blockIdx.x * 256 + threadIdx.x;  // float4 index, total 196608
  const float* src;
  __half* dst;
  int loc;
  if (j < 16384) { src = wq; dst = g_wqkv_h; loc = j; }
  else if (j < 32768) { src = wk; dst = g_wqkv_h + 65536; loc = j - 16384; }
  else if (j < 49152) { src = wv; dst = g_wqkv_h + 131072; loc = j - 32768; }
  else if (j < 65536) { src = wo; dst = g_wo_h; loc = j - 49152; }
  else if (j < 131072) { src = w1; dst = g_w1_h; loc = j - 65536; }
  else { src = w2; dst = g_w2_h; loc = j - 131072; }
  float4 v = ((const float4*)src)[loc];
  __half h[4];
  h[0] = __float2half(v.x);
  h[1] = __float2half(v.y);
  h[2] = __float2half(v.z);
  h[3] = __float2half(v.w);
  *(uint2*)(dst + loc * 4) = *(uint2*)h;
  int g = j;
  if (g < 256) g_bqkv[g] = bq[g];
  else if (g < 512) g_bqkv[g] = bk[g - 256];
  else if (g < 768) g_bqkv[g] = bv[g - 512];
}

// ---------------- HMMA fp16 GEMM, cp.async 4-stage pipeline ----------------
// CTA 128x128, K-slab 32, warp tile 64x32. All LDSM issued up front per slab,
// then 64 back-to-back MMAs. fp16 epilogues staged through smem -> STG.128.
template <int EPI>
__global__ void __launch_bounds__(256, 2) gemm_mma(
    const __half* __restrict__ A, const __half* __restrict__ B,
    const float* __restrict__ bias, float* __restrict__ out,
    __half* __restrict__ out_h, const float* __restrict__ extra, int K) {
  extern __shared__ char smraw[];
  const int STG = 20480;
  int tid = threadIdx.x, wid = tid >> 5, lane = tid & 31;
  int warp_row = wid >> 2, warp_col = wid & 3;
  int row0 = blockIdx.y * 128, col0 = blockIdx.x * 128;
  uint32_t sm = smem_u32(smraw);

  float acc[4][4][4];
#pragma unroll
  for (int mi = 0; mi < 4; mi++)
#pragma unroll
    for (int ni = 0; ni < 4; ni++)
#pragma unroll
      for (int u = 0; u < 4; u++) acc[mi][ni][u] = 0.0f;

  int lrow = tid >> 2;
  int lchunk = tid & 3;
  int nslabs = K >> 5;

  const __half* Ab = A + (size_t)row0 * K + lchunk * 8;
  const __half* Bb = B + (size_t)col0 * K + lchunk * 8;
  uint32_t soff = lrow * 80 + lchunk * 16;

#pragma unroll
  for (int p = 0; p < 3; p++) {
    uint32_t st = sm + p * STG;
    int k0 = p * 32;
#pragma unroll
    for (int r = 0; r < 2; r++) {
      int row = lrow + r * 64;
      cp16(st + soff + r * 64 * 80, Ab + (size_t)row * K + k0);
      cp16(st + 10240 + soff + r * 64 * 80, Bb + (size_t)row * K + k0);
    }
    CP_COMMIT();
  }

  int a_r = warp_row * 64 + (lane & 15);
  int b_r = warp_col * 32 + (lane & 15);
  int oct = lane >> 4;

  for (int s = 0; s < nslabs; s++) {
    CP_WAIT2();
    __syncthreads();
    if (s + 3 < nslabs) {
      uint32_t st = sm + ((s + 3) & 3) * STG;
      int k0 = (s + 3) * 32;
#pragma unroll
      for (int r = 0; r < 2; r++) {
        int row = lrow + r * 64;
        cp16(st + soff + r * 64 * 80, Ab + (size_t)row * K + k0);
        cp16(st + 10240 + soff + r * 64 * 80, Bb + (size_t)row * K + k0);
      }
    }
    CP_COMMIT();

    uint32_t st = sm + (s & 3) * STG;
    // all fragment loads up front (both kk halves) -> deep LDSM pipeline
    uint32_t ah[2][4][4], bh[2][2][4];
#pragma unroll
    for (int kk = 0; kk < 2; kk++) {
#pragma unroll
      for (int nb = 0; nb < 2; nb++) {
        uint32_t addr = st + 10240 + (b_r + nb * 16) * 80 + (2 * kk + oct) * 16;
        LDSM4(bh[kk][nb], addr);
      }
#pragma unroll
      for (int mi = 0; mi < 4; mi++) {
        uint32_t addr = st + (a_r + mi * 16) * 80 + (2 * kk + oct) * 16;
        LDSM4(ah[kk][mi], addr);
      }
    }
#pragma unroll
    for (int kk = 0; kk < 2; kk++)
#pragma unroll
      for (int mi = 0; mi < 4; mi++)
#pragma unroll
        for (int ni = 0; ni < 4; ni++) {
          int nb = ni >> 1, up = ni & 1;
          MMA16816(acc[mi][ni], ah[kk][mi], bh[kk][nb][up], bh[kk][nb][up + 2]);
        }
  }

  // drain async groups, then stage buffers are reusable for epilogue
  CP_WAIT0();
  __syncthreads();

  int group = lane >> 2, tig = lane & 3;

  if (EPI == 0 || EPI == 2) {
    // fp16 outputs: stage 8x32 fp16 per warp in smem, emit STG.128 (64B/quad)
    float2 bb[4];
#pragma unroll
    for (int ni = 0; ni < 4; ni++)
      bb[ni] = *(const float2*)(bias + col0 + warp_col * 32 + ni * 8 + tig * 2);
    uint32_t sbase = sm + wid * 512;
    char* sbc = smraw + wid * 512;
#pragma unroll
    for (int mi = 0; mi < 4; mi++) {
#pragma unroll
      for (int half = 0; half < 2; half++) {
#pragma unroll
        for (int ni = 0; ni < 4; ni++) {
          float v0 = acc[mi][ni][2 * half + 0] + bb[ni].x;
          float v1 = acc[mi][ni][2 * half + 1] + bb[ni].y;
          if (EPI == 2) {
            v0 = 0.5f * v0 * (1.0f + erff(v0 * 0.7071067811865476f));
            v1 = 0.5f * v1 * (1.0f + erff(v1 * 0.7071067811865476f));
          }
          __half2 hv = __floats2half2_rn(v0, v1);
          *(__half2*)(sbc + group * 64 + ni * 16 + tig * 4) = hv;
        }
        __syncwarp();
        uint4 pkt;
        asm volatile("ld.shared.v4.u32 {%0,%1,%2,%3}, [%4];"
                     : "=r"(pkt.x), "=r"(pkt.y), "=r"(pkt.z), "=r"(pkt.w)
                     : "r"(sbase + group * 64 + tig * 16));
        int r = row0 + warp_row * 64 + mi * 16 + group + 8 * half;
        int c = col0 + warp_col * 32 + tig * 8;
        if (EPI == 0) {
          int sel = c >> 8, cw = c & 255;
          int head = cw >> 5, d = cw & 31;
          int win = r >> 6, n = r & 63;
          *(uint4*)(g_qkv + (size_t)sel * (TOK * CDIM) + (size_t)win * 16384 +
                    head * 2048 + n * 32 + d) = pkt;
        } else {
          *(uint4*)(out_h + (size_t)r * MLPD + c) = pkt;
        }
        __syncwarp();
      }
    }
  } else {
#pragma unroll
    for (int mi = 0; mi < 4; mi++) {
#pragma unroll
      for (int half = 0; half < 2; half++) {
        int r = row0 + warp_row * 64 + mi * 16 + group + 8 * half;
        if (EPI == 1) {
          int dst = map_shift(r);
#pragma unroll
          for (int ni = 0; ni < 4; ni++) {
            int c = col0 + warp_col * 32 + ni * 8 + tig * 2;
            size_t off = (size_t)dst * 256 + c;
            float2 bb = *(const float2*)(bias + c);
            float2 ex = *(const float2*)(extra + off);
            float2 v;
            v.x = acc[mi][ni][2 * half + 0] + bb.x + ex.x;
            v.y = acc[mi][ni][2 * half + 1] + bb.y + ex.y;
            *(float2*)(out + off) = v;
          }
        } else {
#pragma unroll
          for (int ni = 0; ni < 4; ni++) {
            int c = col0 + warp_col * 32 + ni * 8 + tig * 2;
            size_t off = (size_t)r * 256 + c;
            float2 bb = *(const float2*)(bias + c);
            float2 ex = *(const float2*)(extra + off);
            float2 v;
            v.x = acc[mi][ni][2 * half + 0] + bb.x + ex.x;
            v.y = acc[mi][ni][2 * half + 1] + bb.y + ex.y;
            *(float2*)(out + off) = v;
          }
        }
      }
    }
  }
}

// ---------------- tensor-core windowed attention --------------------------
__global__ void __launch_bounds__(256) attn_mma(
    const float* __restrict__ rel_table) {
  extern __shared__ char smraw[];
  const int QOFF = 0, KOFF = 20480, VOFF = 40960, ROFF = 61440;
  int tid = threadIdx.x, wid = tid >> 5, lane = tid & 31;
  int win = blockIdx.x >> 1;
  int hgrp = (blockIdx.x & 1) * 4;
  uint32_t smb = smem_u32(smraw);

  size_t gbase = (size_t)win * 16384 + (size_t)hgrp * 2048;
  const __half* qg = g_qkv + gbase;
  const __half* kg = g_qkv + (size_t)TOK * CDIM + gbase;
  const __half* vg = g_qkv + 2 * (size_t)TOK * CDIM + gbase;

#pragma unroll
  for (int p = 0; p < 4; p++) {
    int e = p * 2048 + tid * 8;
    int hl = e >> 11, r = (e >> 5) & 63, ck = (e >> 3) & 3;
    uint32_t so = hl * 5120 + r * 80 + ck * 16;
    *(uint4*)(smraw + QOFF + so) = *(const uint4*)(qg + e);
    *(uint4*)(smraw + KOFF + so) = *(const uint4*)(kg + e);
    *(uint4*)(smraw + VOFF + so) = *(const uint4*)(vg + e);
  }
  for (int i = tid; i < 900; i += 256) {
    int hl = i / 225, idx = i - hl * 225;
    *(float*)(smraw + ROFF + hl * 900 + idx * 4) = rel_table[idx * 8 + hgrp + hl];
  }
  __syncthreads();

  int head_l = wid >> 1;
  int rb = (wid & 1) * 32;
  uint32_t qb = smb + QOFF + head_l * 5120;
  uint32_t kb = smb + KOFF + head_l * 5120;
  uint32_t vb = smb + VOFF + head_l * 5120;
  const float* relh = (const float*)(smraw + ROFF + head_l * 900);

  int g = lane >> 2, t = lane & 3;
  int oct = lane >> 4;

  uint32_t qa[2][2][4];
#pragma unroll
  for (int mi = 0; mi < 2; mi++)
#pragma unroll
    for (int kt = 0; kt < 2; kt++) {
      uint32_t addr = qb + (rb + mi * 16 + (lane & 15)) * 80 +
                      (oct * 8 + kt * 16) * 2;
      LDSM4(qa[mi][kt], addr);
    }

  uint32_t kf[2][8][2];
#pragma unroll
  for (int j = 0; j < 4; j++)
#pragma unroll
    for (int kt = 0; kt < 2; kt++) {
      uint32_t r4[4];
      uint32_t addr = kb + (j * 16 + (lane & 15)) * 80 + (kt * 16 + oct * 8) * 2;
      LDSM4(r4, addr);
      kf[kt][j * 2 + 0][0] = r4[0];
      kf[kt][j * 2 + 0][1] = r4[2];
      kf[kt][j * 2 + 1][0] = r4[1];
      kf[kt][j * 2 + 1][1] = r4[3];
    }

  float sc[2][8][4];
#pragma unroll
  for (int mi = 0; mi < 2; mi++)
#pragma unroll
    for (int nt = 0; nt < 8; nt++) {
#pragma unroll
      for (int u = 0; u < 4; u++) sc[mi][nt][u] = 0.0f;
      MMA16816(sc[mi][nt], qa[mi][0], kf[0][nt][0], kf[0][nt][1]);
      MMA16816(sc[mi][nt], qa[mi][1], kf[1][nt][0], kf[1][nt][1]);
    }

  int nw = win & 63;
  bool eh = (nw >> 3) == 7, ew = (nw & 7) == 7;
  const float scale = 0.17677669529663687f;
  float inv[2][2];
#pragma unroll
  for (int mi = 0; mi < 2; mi++) {
    float rmax[2] = {-1e30f, -1e30f};
#pragma unroll
    for (int h2 = 0; h2 < 2; h2++) {
      int n = rb + mi * 16 + g + 8 * h2;
      int ni_ = n >> 3, nj = n & 7;
      int ridn = (eh ? (ni_ < 4 ? 1 : 2) : 0) * 3 + (ew ? (nj < 4 ? 1 : 2) : 0);
#pragma unroll
      for (int nt = 0; nt < 8; nt++) {
#pragma unroll
        for (int j = 0; j < 2; j++) {
          int m = nt * 8 + 2 * t + j;
          int mi_ = m >> 3, mj = m & 7;
          int ridm = (eh ? (mi_ < 4 ? 1 : 2) : 0) * 3 + (ew ? (mj < 4 ? 1 : 2) : 0);
          float s = sc[mi][nt][2 * h2 + j] * scale +
                    relh[(ni_ - mi_ + 7) * 15 + (nj - mj + 7)];
          if (ridn != ridm) s -= 100.0f;
          sc[mi][nt][2 * h2 + j] = s;
          rmax[h2] = fmaxf(rmax[h2], s);
        }
      }
    }
#pragma unroll
    for (int h2 = 0; h2 < 2; h2++) {
      rmax[h2] = fmaxf(rmax[h2], __shfl_xor_sync(0xffffffffu, rmax[h2], 1));
      rmax[h2] = fmaxf(rmax[h2], __shfl_xor_sync(0xffffffffu, rmax[h2], 2));
    }
    float rsum[2] = {0.0f, 0.0f};
#pragma unroll
    for (int nt = 0; nt < 8; nt++)
#pragma unroll
      for (int u = 0; u < 4; u++) {
        int h2 = u >> 1;
        float e = __expf(sc[mi][nt][u] - rmax[h2]);
        sc[mi][nt][u] = e;
        rsum[h2] += e;
      }
#pragma unroll
    for (int h2 = 0; h2 < 2; h2++) {
      rsum[h2] += __shfl_xor_sync(0xffffffffu, rsum[h2], 1);
      rsum[h2] += __shfl_xor_sync(0xffffffffu, rsum[h2], 2);
      inv[mi][h2] = 1.0f / rsum[h2];
    }
  }

  uint32_t ph[2][4][4];
#pragma unroll
  for (int mi = 0; mi < 2; mi++)
#pragma unroll
    for (int kt = 0; kt < 4; kt++) {
      __half2 a0 = __floats2half2_rn(sc[mi][2 * kt][0], sc[mi][2 * kt][1]);
      __half2 a1 = __floats2half2_rn(sc[mi][2 * kt][2], sc[mi][2 * kt][3]);
      __half2 a2 = __floats2half2_rn(sc[mi][2 * kt + 1][0], sc[mi][2 * kt + 1][1]);
      __half2 a3 = __floats2half2_rn(sc[mi][2 * kt + 1][2], sc[mi][2 * kt + 1][3]);
      ph[mi][kt][0] = *(uint32_t*)&a0;
      ph[mi][kt][1] = *(uint32_t*)&a1;
      ph[mi][kt][2] = *(uint32_t*)&a2;
      ph[mi][kt][3] = *(uint32_t*)&a3;
    }

  uint32_t vf[4][4][2];
#pragma unroll
  for (int kt = 0; kt < 4; kt++)
#pragma unroll
    for (int np = 0; np < 2; np++) {
      uint32_t r4[4];
      uint32_t addr = vb + (kt * 16 + (lane & 15)) * 80 + (np * 16 + oct * 8) * 2;
      LDSM4T(r4, addr);
      vf[kt][np * 2 + 0][0] = r4[0];
      vf[kt][np * 2 + 0][1] = r4[1];
      vf[kt][np * 2 + 1][0] = r4[2];
      vf[kt][np * 2 + 1][1] = r4[3];
    }

  float oc[2][4][4];
#pragma unroll
  for (int mi = 0; mi < 2; mi++)
#pragma unroll
    for (int ni = 0; ni < 4; ni++) {
#pragma unroll
      for (int u = 0; u < 4; u++) oc[mi][ni][u] = 0.0f;
#pragma unroll
      for (int kt = 0; kt < 4; kt++)
        MMA16816(oc[mi][ni], ph[mi][kt], vf[kt][ni][0], vf[kt][ni][1]);
    }

  int head = hgrp + head_l;
#pragma unroll
  for (int mi = 0; mi < 2; mi++)
#pragma unroll
    for (int h2 = 0; h2 < 2; h2++) {
      int n = rb + mi * 16 + g + 8 * h2;
      float iv = inv[mi][h2];
#pragma unroll
      for (int ni = 0; ni < 4; ni++) {
        int d = ni * 8 + 2 * t;
        __half2 hv = __floats2half2_rn(oc[mi][ni][2 * h2 + 0] * iv,
                                       oc[mi][ni][2 * h2 + 1] * iv);
        *(__half2*)(g_ctx_h + ((size_t)win * 64 + n) * 256 + head * 32 + d) = hv;
      }
    }
}

// ---------------- host ----------------
extern "C" void kernel_launch(void* const* d_in, const int* in_sizes, int n_in,
                              void* d_out, int out_size) {
  (void)in_sizes; (void)n_in; (void)out_size;
  const float* hs   = (const float*)d_in[0];
  const float* ln1g = (const float*)d_in[1];
  const float* ln1b = (const float*)d_in[2];
  const float* wq   = (const float*)d_in[3];
  const float* bq   = (const float*)d_in[4];
  const float* wk   = (const float*)d_in[5];
  const float* bk   = (const float*)d_in[6];
  const float* wv   = (const float*)d_in[7];
  const float* bv   = (const float*)d_in[8];
  const float* rel  = (const float*)d_in[9];
  const float* wo   = (const float*)d_in[10];
  const float* bo   = (const float*)d_in[11];
  const float* ln2g = (const float*)d_in[12];
  const float* ln2b = (const float*)d_in[13];
  const float* w1   = (const float*)d_in[14];
  const float* b1   = (const float*)d_in[15];
  const float* w2   = (const float*)d_in[16];
  const float* b2   = (const float*)d_in[17];
  float* out = (float*)d_out;

  __half *xh, *yh, *cxh, *ith, *wqkvh, *woh, *w1h, *w2h;
  float *bqkv, *hid;
  cudaGetSymbolAddress((void**)&xh, g_x_h);
  cudaGetSymbolAddress((void**)&yh, g_y_h);
  cudaGetSymbolAddress((void**)&cxh, g_ctx_h);
  cudaGetSymbolAddress((void**)&ith, g_int_h);
  cudaGetSymbolAddress((void**)&wqkvh, g_wqkv_h);
  cudaGetSymbolAddress((void**)&woh, g_wo_h);
  cudaGetSymbolAddress((void**)&w1h, g_w1_h);
  cudaGetSymbolAddress((void**)&w2h, g_w2_h);
  cudaGetSymbolAddress((void**)&bqkv, g_bqkv);
  cudaGetSymbolAddress((void**)&hid, g_hidden);

  const int SMSZ = 4 * 20480;
  cudaFuncSetAttribute(gemm_mma<0>, cudaFuncAttributeMaxDynamicSharedMemorySize, SMSZ);
  cudaFuncSetAttribute(gemm_mma<1>, cudaFuncAttributeMaxDynamicSharedMemorySize, SMSZ);
  cudaFuncSetAttribute(gemm_mma<2>, cudaFuncAttributeMaxDynamicSharedMemorySize, SMSZ);
  cudaFuncSetAttribute(gemm_mma<3>, cudaFuncAttributeMaxDynamicSharedMemorySize, SMSZ);
  const int ASM = 61440 + 3600;
  cudaFuncSetAttribute(attn_mma, cudaFuncAttributeMaxDynamicSharedMemorySize, ASM);

  prep_weights<<<768, 256>>>(wq, wk, wv, wo, w1, w2, bq, bk, bv);

  ln_h<true><<<4096, 256>>>(hs, ln1g, ln1b, xh);

  gemm_mma<0><<<dim3(6, 256), 256, SMSZ>>>(xh, wqkvh, bqkv, nullptr, nullptr,
                                           nullptr, 256);

  attn_mma<<<1024, 256, ASM>>>(rel);

  gemm_mma<1><<<dim3(2, 256), 256, SMSZ>>>(cxh, woh, bo, hid, nullptr, hs, 256);

  ln_h<false><<<4096, 256>>>(hid, ln2g, ln2b, yh);

  gemm_mma<2><<<dim3(8, 256), 256, SMSZ>>>(yh, w1h, b1, nullptr, ith, nullptr, 256);

  gemm_mma<3><<<dim3(2, 256), 256, SMSZ>>>(ith, w2h, b2, out, nullptr, hid, 1024);
}

// round 9
// speedup vs baseline: 5.6602x; 1.0037x over previous
#include <cuda_runtime.h>
#include <cuda_fp16.h>
#include <math.h>
#include <stdint.h>

#define TOK 32768
#define CDIM 256
#define MLPD 1024

// ---------------- device scratch ----------------
__device__ __half g_x_h[TOK * CDIM];        // LN1 output (windowed order)
__device__ __half g_y_h[TOK * CDIM];        // LN2 output
__device__ __half g_ctx_h[TOK * CDIM];      // attention context (windowed order)
__device__ __half g_int_h[TOK * MLPD];      // MLP hidden
__device__ __half g_wqkv_h[3 * CDIM * CDIM];
__device__ __half g_wo_h[CDIM * CDIM];
__device__ __half g_w1_h[MLPD * CDIM];
__device__ __half g_w2_h[CDIM * MLPD];
__device__ float g_bqkv[3 * CDIM];
__device__ __half g_qkv[3 * TOK * CDIM];    // [sel][win][head][n][d]
__device__ float g_hidden[TOK * CDIM];

// ---------------- helpers ----------------
__device__ __forceinline__ uint32_t smem_u32(const void* p) {
  uint32_t a;
  asm("{ .reg .u64 t; cvta.to.shared.u64 t, %1; cvt.u32.u64 %0, t; }"
      : "=r"(a) : "l"(p));
  return a;
}

__device__ __forceinline__ void cp16(uint32_t smem, const void* g) {
  asm volatile("cp.async.cg.shared.global [%0], [%1], 16;" :: "r"(smem), "l"(g));
}
#define CP_COMMIT() asm volatile("cp.async.commit_group;" ::: "memory")
#define CP_WAIT2() asm volatile("cp.async.wait_group 2;" ::: "memory")
#define CP_WAIT0() asm volatile("cp.async.wait_group 0;" ::: "memory")

#define LDSM4(r, addr) \
  asm volatile("ldmatrix.sync.aligned.m8n8.x4.shared.b16 {%0,%1,%2,%3}, [%4];" \
               : "=r"((r)[0]), "=r"((r)[1]), "=r"((r)[2]), "=r"((r)[3]) \
               : "r"(addr))

#define LDSM4T(r, addr) \
  asm volatile("ldmatrix.sync.aligned.m8n8.x4.trans.shared.b16 {%0,%1,%2,%3}, [%4];" \
               : "=r"((r)[0]), "=r"((r)[1]), "=r"((r)[2]), "=r"((r)[3]) \
               : "r"(addr))

#define MMA16816(d, a, b0, b1) \
  asm volatile( \
      "mma.sync.aligned.m16n8k16.row.col.f32.f16.f16.f32 " \
      "{%0,%1,%2,%3}, {%4,%5,%6,%7}, {%8,%9}, {%0,%1,%2,%3};" \
      : "+f"((d)[0]), "+f"((d)[1]), "+f"((d)[2]), "+f"((d)[3]) \
      : "r"((a)[0]), "r"((a)[1]), "r"((a)[2]), "r"((a)[3]), \
        "r"(b0), "r"(b1))

// windowed token index -> original token index (+4 cyclic shift)
__device__ __forceinline__ int map_shift(int t) {
  int b = t >> 12, rr = t & 4095;
  int win = rr >> 6, n = rr & 63;
  int wh = win >> 3, ww = win & 7, i = n >> 3, j = n & 7;
  int h = (wh * 8 + i + 4) & 63;
  int w = (ww * 8 + j + 4) & 63;
  return (b << 12) + (h << 6) + w;
}

// ---------------- LayerNorm -> fp16 (one warp per token) -------------------
template <bool GATHER>
__device__ __forceinline__ void ln_body(
    const float* __restrict__ x, const float* __restrict__ gam,
    const float* __restrict__ bet, __half* __restrict__ oh, int blk) {
  int warp = threadIdx.x >> 5, lane = threadIdx.x & 31;
  int t = blk * 8 + warp;
  int src = GATHER ? map_shift(t) : t;
  const float4* xr = (const float4*)(x + (size_t)src * CDIM);
  float4 v0 = xr[lane], v1 = xr[lane + 32];
  float s = v0.x + v0.y + v0.z + v0.w + v1.x + v1.y + v1.z + v1.w;
  float q = v0.x * v0.x + v0.y * v0.y + v0.z * v0.z + v0.w * v0.w +
            v1.x * v1.x + v1.y * v1.y + v1.z * v1.z + v1.w * v1.w;
#pragma unroll
  for (int o = 16; o; o >>= 1) {
    s += __shfl_xor_sync(0xffffffffu, s, o);
    q += __shfl_xor_sync(0xffffffffu, q, o);
  }
  float mean = s * (1.0f / 256.0f);
  float var = q * (1.0f / 256.0f) - mean * mean;
  float rs = rsqrtf(var + 1e-5f);
  const float4* g4 = (const float4*)gam;
  const float4* b4 = (const float4*)bet;
  __half h[4];
  {
    float4 ga = g4[lane], be = b4[lane];
    h[0] = __float2half((v0.x - mean) * rs * ga.x + be.x);
    h[1] = __float2half((v0.y - mean) * rs * ga.y + be.y);
    h[2] = __float2half((v0.z - mean) * rs * ga.z + be.z);
    h[3] = __float2half((v0.w - mean) * rs * ga.w + be.w);
    *(uint2*)(oh + (size_t)t * CDIM + lane * 4) = *(uint2*)h;
  }
  {
    float4 ga = g4[lane + 32], be = b4[lane + 32];
    h[0] = __float2half((v1.x - mean) * rs * ga.x + be.x);
    h[1] = __float2half((v1.y - mean) * rs * ga.y + be.y);
    h[2] = __float2half((v1.z - mean) * rs * ga.z + be.z);
    h[3] = __float2half((v1.w - mean) * rs * ga.w + be.w);
    *(uint2*)(oh + (size_t)t * CDIM + 128 + lane * 4) = *(uint2*)h;
  }
}

__global__ void __launch_bounds__(256) ln2_k(
    const float* __restrict__ x, const float* __restrict__ gam,
    const float* __restrict__ bet, __half* __restrict__ oh) {
  ln_body<false>(x, gam, bet, oh, blockIdx.x);
}

// ---------------- fused: LN1 (blocks 0..4095) + weight prep (4096..4863) ---
__global__ void __launch_bounds__(256) prep_ln1(
    const float* __restrict__ hs, const float* __restrict__ ln1g,
    const float* __restrict__ ln1b,
    const float* __restrict__ wq, const float* __restrict__ wk,
    const float* __restrict__ wv, const float* __restrict__ wo,
    const float* __restrict__ w1, const float* __restrict__ w2,
    const float* __restrict__ bq, const float* __restrict__ bk,
    const float* __restrict__ bv) {
  int b = blockIdx.x;
  if (b < 4096) {
    ln_body<true>(hs, ln1g, ln1b, g_x_h, b);
    return;
  }
  int j = (b - 4096) * 256 + threadIdx.x;  // float4 index, total 196608
  const float* src;
  __half* dst;
  int loc;
  if (j < 16384) { src = wq; dst = g_wqkv_h; loc = j; }
  else if (j < 32768) { src = wk; dst = g_wqkv_h + 65536; loc = j - 16384; }
  else if (j < 49152) { src = wv; dst = g_wqkv_h + 131072; loc = j - 32768; }
  else if (j < 65536) { src = wo; dst = g_wo_h; loc = j - 49152; }
  else if (j < 131072) { src = w1; dst = g_w1_h; loc = j - 65536; }
  else { src = w2; dst = g_w2_h; loc = j - 131072; }
  float4 v = ((const float4*)src)[loc];
  __half h[4];
  h[0] = __float2half(v.x);
  h[1] = __float2half(v.y);
  h[2] = __float2half(v.z);
  h[3] = __float2half(v.w);
  *(uint2*)(dst + loc * 4) = *(uint2*)h;
  if (j < 256) g_bqkv[j] = bq[j];
  else if (j < 512) g_bqkv[j] = bk[j - 256];
  else if (j < 768) g_bqkv[j] = bv[j - 512];
}

// ---------------- HMMA fp16 GEMM, cp.async 4-stage pipeline ----------------
// CTA 128x128, K-slab 32, warp tile 64x32. Per-kk fragment loads (no spills),
// fp16 epilogues staged through smem -> STG.128.
template <int EPI>
__global__ void __launch_bounds__(256, 2) gemm_mma(
    const __half* __restrict__ A, const __half* __restrict__ B,
    const float* __restrict__ bias, float* __restrict__ out,
    __half* __restrict__ out_h, const float* __restrict__ extra, int K) {
  extern __shared__ char smraw[];
  const int STG = 20480;
  int tid = threadIdx.x, wid = tid >> 5, lane = tid & 31;
  int warp_row = wid >> 2, warp_col = wid & 3;
  int row0 = blockIdx.y * 128, col0 = blockIdx.x * 128;
  uint32_t sm = smem_u32(smraw);

  float acc[4][4][4];
#pragma unroll
  for (int mi = 0; mi < 4; mi++)
#pragma unroll
    for (int ni = 0; ni < 4; ni++)
#pragma unroll
      for (int u = 0; u < 4; u++) acc[mi][ni][u] = 0.0f;

  int lrow = tid >> 2;
  int lchunk = tid & 3;
  int nslabs = K >> 5;

  const __half* Ab = A + (size_t)row0 * K + lchunk * 8;
  const __half* Bb = B + (size_t)col0 * K + lchunk * 8;
  uint32_t soff = lrow * 80 + lchunk * 16;

#pragma unroll
  for (int p = 0; p < 3; p++) {
    uint32_t st = sm + p * STG;
    int k0 = p * 32;
#pragma unroll
    for (int r = 0; r < 2; r++) {
      int row = lrow + r * 64;
      cp16(st + soff + r * 64 * 80, Ab + (size_t)row * K + k0);
      cp16(st + 10240 + soff + r * 64 * 80, Bb + (size_t)row * K + k0);
    }
    CP_COMMIT();
  }

  int a_r = warp_row * 64 + (lane & 15);
  int b_r = warp_col * 32 + (lane & 15);
  int oct = lane >> 4;

  for (int s = 0; s < nslabs; s++) {
    CP_WAIT2();
    __syncthreads();
    if (s + 3 < nslabs) {
      uint32_t st = sm + ((s + 3) & 3) * STG;
      int k0 = (s + 3) * 32;
#pragma unroll
      for (int r = 0; r < 2; r++) {
        int row = lrow + r * 64;
        cp16(st + soff + r * 64 * 80, Ab + (size_t)row * K + k0);
        cp16(st + 10240 + soff + r * 64 * 80, Bb + (size_t)row * K + k0);
      }
    }
    CP_COMMIT();

    uint32_t st = sm + (s & 3) * STG;
#pragma unroll
    for (int kk = 0; kk < 2; kk++) {
      uint32_t bh[2][4], ah[4][4];
#pragma unroll
      for (int nb = 0; nb < 2; nb++) {
        uint32_t addr = st + 10240 + (b_r + nb * 16) * 80 + (2 * kk + oct) * 16;
        LDSM4(bh[nb], addr);
      }
#pragma unroll
      for (int mi = 0; mi < 4; mi++) {
        uint32_t addr = st + (a_r + mi * 16) * 80 + (2 * kk + oct) * 16;
        LDSM4(ah[mi], addr);
      }
#pragma unroll
      for (int mi = 0; mi < 4; mi++)
#pragma unroll
        for (int ni = 0; ni < 4; ni++) {
          int nb = ni >> 1, up = ni & 1;
          MMA16816(acc[mi][ni], ah[mi], bh[nb][up], bh[nb][up + 2]);
        }
    }
  }

  // drain async groups; stage buffers reusable for epilogue
  CP_WAIT0();
  __syncthreads();

  int group = lane >> 2, tig = lane & 3;

  if (EPI == 0 || EPI == 2) {
    // fp16 outputs: stage 8x32 fp16 per warp in smem, emit STG.128 (64B/quad)
    float2 bb[4];
#pragma unroll
    for (int ni = 0; ni < 4; ni++)
      bb[ni] = *(const float2*)(bias + col0 + warp_col * 32 + ni * 8 + tig * 2);
    uint32_t sbase = sm + wid * 512;
    char* sbc = smraw + wid * 512;
#pragma unroll
    for (int mi = 0; mi < 4; mi++) {
#pragma unroll
      for (int half = 0; half < 2; half++) {
#pragma unroll
        for (int ni = 0; ni < 4; ni++) {
          float v0 = acc[mi][ni][2 * half + 0] + bb[ni].x;
          float v1 = acc[mi][ni][2 * half + 1] + bb[ni].y;
          if (EPI == 2) {
            v0 = 0.5f * v0 * (1.0f + erff(v0 * 0.7071067811865476f));
            v1 = 0.5f * v1 * (1.0f + erff(v1 * 0.7071067811865476f));
          }
          __half2 hv = __floats2half2_rn(v0, v1);
          *(__half2*)(sbc + group * 64 + ni * 16 + tig * 4) = hv;
        }
        __syncwarp();
        uint4 pkt;
        asm volatile("ld.shared.v4.u32 {%0,%1,%2,%3}, [%4];"
                     : "=r"(pkt.x), "=r"(pkt.y), "=r"(pkt.z), "=r"(pkt.w)
                     : "r"(sbase + group * 64 + tig * 16));
        int r = row0 + warp_row * 64 + mi * 16 + group + 8 * half;
        int c = col0 + warp_col * 32 + tig * 8;
        if (EPI == 0) {
          int sel = c >> 8, cw = c & 255;
          int head = cw >> 5, d = cw & 31;
          int win = r >> 6, n = r & 63;
          *(uint4*)(g_qkv + (size_t)sel * (TOK * CDIM) + (size_t)win * 16384 +
                    head * 2048 + n * 32 + d) = pkt;
        } else {
          *(uint4*)(out_h + (size_t)r * MLPD + c) = pkt;
        }
        __syncwarp();
      }
    }
  } else {
#pragma unroll
    for (int mi = 0; mi < 4; mi++) {
#pragma unroll
      for (int half = 0; half < 2; half++) {
        int r = row0 + warp_row * 64 + mi * 16 + group + 8 * half;
        int dst = (EPI == 1) ? map_shift(r) : r;
#pragma unroll
        for (int ni = 0; ni < 4; ni++) {
          int c = col0 + warp_col * 32 + ni * 8 + tig * 2;
          size_t off = (size_t)dst * 256 + c;
          float2 bb = *(const float2*)(bias + c);
          float2 ex = *(const float2*)(extra + off);
          float2 v;
          v.x = acc[mi][ni][2 * half + 0] + bb.x + ex.x;
          v.y = acc[mi][ni][2 * half + 1] + bb.y + ex.y;
          *(float2*)(out + off) = v;
        }
      }
    }
  }
}

// ---------------- tensor-core windowed attention --------------------------
__global__ void __launch_bounds__(256) attn_mma(
    const float* __restrict__ rel_table) {
  extern __shared__ char smraw[];
  const int QOFF = 0, KOFF = 20480, VOFF = 40960, ROFF = 61440;
  int tid = threadIdx.x, wid = tid >> 5, lane = tid & 31;
  int win = blockIdx.x >> 1;
  int hgrp = (blockIdx.x & 1) * 4;
  uint32_t smb = smem_u32(smraw);

  size_t gbase = (size_t)win * 16384 + (size_t)hgrp * 2048;
  const __half* qg = g_qkv + gbase;
  const __half* kg = g_qkv + (size_t)TOK * CDIM + gbase;
  const __half* vg = g_qkv + 2 * (size_t)TOK * CDIM + gbase;

#pragma unroll
  for (int p = 0; p < 4; p++) {
    int e = p * 2048 + tid * 8;
    int hl = e >> 11, r = (e >> 5) & 63, ck = (e >> 3) & 3;
    uint32_t so = hl * 5120 + r * 80 + ck * 16;
    *(uint4*)(smraw + QOFF + so) = *(const uint4*)(qg + e);
    *(uint4*)(smraw + KOFF + so) = *(const uint4*)(kg + e);
    *(uint4*)(smraw + VOFF + so) = *(const uint4*)(vg + e);
  }
  for (int i = tid; i < 900; i += 256) {
    int hl = i / 225, idx = i - hl * 225;
    *(float*)(smraw + ROFF + hl * 900 + idx * 4) = rel_table[idx * 8 + hgrp + hl];
  }
  __syncthreads();

  int head_l = wid >> 1;
  int rb = (wid & 1) * 32;
  uint32_t qb = smb + QOFF + head_l * 5120;
  uint32_t kb = smb + KOFF + head_l * 5120;
  uint32_t vb = smb + VOFF + head_l * 5120;
  const float* relh = (const float*)(smraw + ROFF + head_l * 900);

  int g = lane >> 2, t = lane & 3;
  int oct = lane >> 4;

  uint32_t qa[2][2][4];
#pragma unroll
  for (int mi = 0; mi < 2; mi++)
#pragma unroll
    for (int kt = 0; kt < 2; kt++) {
      uint32_t addr = qb + (rb + mi * 16 + (lane & 15)) * 80 +
                      (oct * 8 + kt * 16) * 2;
      LDSM4(qa[mi][kt], addr);
    }

  uint32_t kf[2][8][2];
#pragma unroll
  for (int j = 0; j < 4; j++)
#pragma unroll
    for (int kt = 0; kt < 2; kt++) {
      uint32_t r4[4];
      uint32_t addr = kb + (j * 16 + (lane & 15)) * 80 + (kt * 16 + oct * 8) * 2;
      LDSM4(r4, addr);
      kf[kt][j * 2 + 0][0] = r4[0];
      kf[kt][j * 2 + 0][1] = r4[2];
      kf[kt][j * 2 + 1][0] = r4[1];
      kf[kt][j * 2 + 1][1] = r4[3];
    }

  float sc[2][8][4];
#pragma unroll
  for (int mi = 0; mi < 2; mi++)
#pragma unroll
    for (int nt = 0; nt < 8; nt++) {
#pragma unroll
      for (int u = 0; u < 4; u++) sc[mi][nt][u] = 0.0f;
      MMA16816(sc[mi][nt], qa[mi][0], kf[0][nt][0], kf[0][nt][1]);
      MMA16816(sc[mi][nt], qa[mi][1], kf[1][nt][0], kf[1][nt][1]);
    }

  int nw = win & 63;
  bool eh = (nw >> 3) == 7, ew = (nw & 7) == 7;
  const float scale = 0.17677669529663687f;
  float inv[2][2];
#pragma unroll
  for (int mi = 0; mi < 2; mi++) {
    float rmax[2] = {-1e30f, -1e30f};
#pragma unroll
    for (int h2 = 0; h2 < 2; h2++) {
      int n = rb + mi * 16 + g + 8 * h2;
      int ni_ = n >> 3, nj = n & 7;
      int ridn = (eh ? (ni_ < 4 ? 1 : 2) : 0) * 3 + (ew ? (nj < 4 ? 1 : 2) : 0);
#pragma unroll
      for (int nt = 0; nt < 8; nt++) {
#pragma unroll
        for (int j = 0; j < 2; j++) {
          int m = nt * 8 + 2 * t + j;
          int mi_ = m >> 3, mj = m & 7;
          int ridm = (eh ? (mi_ < 4 ? 1 : 2) : 0) * 3 + (ew ? (mj < 4 ? 1 : 2) : 0);
          float s = sc[mi][nt][2 * h2 + j] * scale +
                    relh[(ni_ - mi_ + 7) * 15 + (nj - mj + 7)];
          if (ridn != ridm) s -= 100.0f;
          sc[mi][nt][2 * h2 + j] = s;
          rmax[h2] = fmaxf(rmax[h2], s);
        }
      }
    }
#pragma unroll
    for (int h2 = 0; h2 < 2; h2++) {
      rmax[h2] = fmaxf(rmax[h2], __shfl_xor_sync(0xffffffffu, rmax[h2], 1));
      rmax[h2] = fmaxf(rmax[h2], __shfl_xor_sync(0xffffffffu, rmax[h2], 2));
    }
    float rsum[2] = {0.0f, 0.0f};
#pragma unroll
    for (int nt = 0; nt < 8; nt++)
#pragma unroll
      for (int u = 0; u < 4; u++) {
        int h2 = u >> 1;
        float e = __expf(sc[mi][nt][u] - rmax[h2]);
        sc[mi][nt][u] = e;
        rsum[h2] += e;
      }
#pragma unroll
    for (int h2 = 0; h2 < 2; h2++) {
      rsum[h2] += __shfl_xor_sync(0xffffffffu, rsum[h2], 1);
      rsum[h2] += __shfl_xor_sync(0xffffffffu, rsum[h2], 2);
      inv[mi][h2] = 1.0f / rsum[h2];
    }
  }

  uint32_t ph[2][4][4];
#pragma unroll
  for (int mi = 0; mi < 2; mi++)
#pragma unroll
    for (int kt = 0; kt < 4; kt++) {
      __half2 a0 = __floats2half2_rn(sc[mi][2 * kt][0], sc[mi][2 * kt][1]);
      __half2 a1 = __floats2half2_rn(sc[mi][2 * kt][2], sc[mi][2 * kt][3]);
      __half2 a2 = __floats2half2_rn(sc[mi][2 * kt + 1][0], sc[mi][2 * kt + 1][1]);
      __half2 a3 = __floats2half2_rn(sc[mi][2 * kt + 1][2], sc[mi][2 * kt + 1][3]);
      ph[mi][kt][0] = *(uint32_t*)&a0;
      ph[mi][kt][1] = *(uint32_t*)&a1;
      ph[mi][kt][2] = *(uint32_t*)&a2;
      ph[mi][kt][3] = *(uint32_t*)&a3;
    }

  uint32_t vf[4][4][2];
#pragma unroll
  for (int kt = 0; kt < 4; kt++)
#pragma unroll
    for (int np = 0; np < 2; np++) {
      uint32_t r4[4];
      uint32_t addr = vb + (kt * 16 + (lane & 15)) * 80 + (np * 16 + oct * 8) * 2;
      LDSM4T(r4, addr);
      vf[kt][np * 2 + 0][0] = r4[0];
      vf[kt][np * 2 + 0][1] = r4[1];
      vf[kt][np * 2 + 1][0] = r4[2];
      vf[kt][np * 2 + 1][1] = r4[3];
    }

  float oc[2][4][4];
#pragma unroll
  for (int mi = 0; mi < 2; mi++)
#pragma unroll
    for (int ni = 0; ni < 4; ni++) {
#pragma unroll
      for (int u = 0; u < 4; u++) oc[mi][ni][u] = 0.0f;
#pragma unroll
      for (int kt = 0; kt < 4; kt++)
        MMA16816(oc[mi][ni], ph[mi][kt], vf[kt][ni][0], vf[kt][ni][1]);
    }

  int head = hgrp + head_l;
#pragma unroll
  for (int mi = 0; mi < 2; mi++)
#pragma unroll
    for (int h2 = 0; h2 < 2; h2++) {
      int n = rb + mi * 16 + g + 8 * h2;
      float iv = inv[mi][h2];
#pragma unroll
      for (int ni = 0; ni < 4; ni++) {
        int d = ni * 8 + 2 * t;
        __half2 hv = __floats2half2_rn(oc[mi][ni][2 * h2 + 0] * iv,
                                       oc[mi][ni][2 * h2 + 1] * iv);
        *(__half2*)(g_ctx_h + ((size_t)win * 64 + n) * 256 + head * 32 + d) = hv;
      }
    }
}

// ---------------- host ----------------
extern "C" void kernel_launch(void* const* d_in, const int* in_sizes, int n_in,
                              void* d_out, int out_size) {
  (void)in_sizes; (void)n_in; (void)out_size;
  const float* hs   = (const float*)d_in[0];
  const float* ln1g = (const float*)d_in[1];
  const float* ln1b = (const float*)d_in[2];
  const float* wq   = (const float*)d_in[3];
  const float* bq   = (const float*)d_in[4];
  const float* wk   = (const float*)d_in[5];
  const float* bk   = (const float*)d_in[6];
  const float* wv   = (const float*)d_in[7];
  const float* bv   = (const float*)d_in[8];
  const float* rel  = (const float*)d_in[9];
  const float* wo   = (const float*)d_in[10];
  const float* bo   = (const float*)d_in[11];
  const float* ln2g = (const float*)d_in[12];
  const float* ln2b = (const float*)d_in[13];
  const float* w1   = (const float*)d_in[14];
  const float* b1   = (const float*)d_in[15];
  const float* w2   = (const float*)d_in[16];
  const float* b2   = (const float*)d_in[17];
  float* out = (float*)d_out;

  __half *xh, *yh, *cxh, *ith, *wqkvh, *woh, *w1h, *w2h;
  float *bqkv, *hid;
  cudaGetSymbolAddress((void**)&xh, g_x_h);
  cudaGetSymbolAddress((void**)&yh, g_y_h);
  cudaGetSymbolAddress((void**)&cxh, g_ctx_h);
  cudaGetSymbolAddress((void**)&ith, g_int_h);
  cudaGetSymbolAddress((void**)&wqkvh, g_wqkv_h);
  cudaGetSymbolAddress((void**)&woh, g_wo_h);
  cudaGetSymbolAddress((void**)&w1h, g_w1_h);
  cudaGetSymbolAddress((void**)&w2h, g_w2_h);
  cudaGetSymbolAddress((void**)&bqkv, g_bqkv);
  cudaGetSymbolAddress((void**)&hid, g_hidden);

  const int SMSZ = 4 * 20480;
  cudaFuncSetAttribute(gemm_mma<0>, cudaFuncAttributeMaxDynamicSharedMemorySize, SMSZ);
  cudaFuncSetAttribute(gemm_mma<1>, cudaFuncAttributeMaxDynamicSharedMemorySize, SMSZ);
  cudaFuncSetAttribute(gemm_mma<2>, cudaFuncAttributeMaxDynamicSharedMemorySize, SMSZ);
  cudaFuncSetAttribute(gemm_mma<3>, cudaFuncAttributeMaxDynamicSharedMemorySize, SMSZ);
  const int ASM = 61440 + 3600;
  cudaFuncSetAttribute(attn_mma, cudaFuncAttributeMaxDynamicSharedMemorySize, ASM);

  prep_ln1<<<4864, 256>>>(hs, ln1g, ln1b, wq, wk, wv, wo, w1, w2, bq, bk, bv);

  gemm_mma<0><<<dim3(6, 256), 256, SMSZ>>>(xh, wqkvh, bqkv, nullptr, nullptr,
                                           nullptr, 256);

  attn_mma<<<1024, 256, ASM>>>(rel);

  gemm_mma<1><<<dim3(2, 256), 256, SMSZ>>>(cxh, woh, bo, hid, nullptr, hs, 256);

  ln2_k<<<4096, 256>>>(hid, ln2g, ln2b, yh);

  gemm_mma<2><<<dim3(8, 256), 256, SMSZ>>>(yh, w1h, b1, nullptr, ith, nullptr, 256);

  gemm_mma<3><<<dim3(2, 256), 256, SMSZ>>>(ith, w2h, b2, out, nullptr, hid, 1024);
}